// round 7
// baseline (speedup 1.0000x reference)
#include <cuda_runtime.h>
#include <cstdint>

// ---------------------------------------------------------------------------
// CharCountCNN — round 7 (= round 6 resubmit after infra failure):
// f32x2 convs with LSU/ALU-minimal inner loop.
//   * shifted duplicate x tile -> pe/po pairs load directly as LDS.128/64,
//     zero mov.b64 packing in the hot loop
//   * weights stored as duplicated (w,w) u64, read 2-per-LDS.128
// ---------------------------------------------------------------------------

constexpr int T_   = 1024;
constexpr int NB   = 128;
constexpr int NCLS = 80;
constexpr int NSTY = 256;
constexpr int NCS  = 64;
constexpr int C1   = 128;
constexpr int C2   = 64;
constexpr int C3   = 32;
constexpr int CIN1W = 400;

// ------------------------- scratch -----------------------------------------
__device__ float d_xin [NB * NCLS * T_];
__device__ int   d_amax[NB * T_];
__device__ float d_gdot[NB * 3 * C1];           // [b][k][o]
__device__ float d_sdot[NB * NCLS * 3 * C1];    // [b][ch][k][o]
__device__ float d_y1  [NB * C1 * T_];
__device__ float d_y2  [NB * C2 * T_];
__device__ float d_y3  [NB * C3 * T_];
__device__ float d_mean1[NB * 32], d_rstd1[NB * 32];
__device__ float d_mean2[NB * 32], d_rstd2[NB * 32];
__device__ float d_mean3[NB * 32], d_rstd3[NB * 32];

// ------------------------- f32x2 helpers -----------------------------------
using u64 = unsigned long long;
__device__ __forceinline__ u64 pk2(float lo, float hi) {
    u64 r;
    asm("mov.b64 %0, {%1, %2};" : "=l"(r) : "f"(lo), "f"(hi));
    return r;
}
__device__ __forceinline__ void upk2(float& lo, float& hi, u64 v) {
    asm("mov.b64 {%0, %1}, %2;" : "=f"(lo), "=f"(hi) : "l"(v));
}
__device__ __forceinline__ void ffma2(u64& d, u64 a, u64 b) {
    asm("fma.rn.f32x2 %0, %1, %2, %0;" : "+l"(d) : "l"(a), "l"(b));
}

// ------------------------- K0: argmax + transpose --------------------------
__global__ void __launch_bounds__(128) k_prep(const float* __restrict__ inp) {
    __shared__ float s[128][NCLS + 1];
    const int b   = blockIdx.y;
    const int t0  = blockIdx.x * 128;
    const int tid = threadIdx.x;

    const float4* row = reinterpret_cast<const float4*>(
        inp + ((size_t)(t0 + tid) * NB + b) * NCLS);

    float best = -3.4e38f;
    int   bi   = 0;
#pragma unroll
    for (int c4 = 0; c4 < NCLS / 4; c4++) {
        float4 v = row[c4];
        int c = c4 * 4;
        s[tid][c + 0] = v.x; s[tid][c + 1] = v.y;
        s[tid][c + 2] = v.z; s[tid][c + 3] = v.w;
        if (v.x > best) { best = v.x; bi = c + 0; }
        if (v.y > best) { best = v.y; bi = c + 1; }
        if (v.z > best) { best = v.z; bi = c + 2; }
        if (v.w > best) { best = v.w; bi = c + 3; }
    }
    d_amax[b * T_ + t0 + tid] = bi;
    __syncthreads();
#pragma unroll 4
    for (int c = 0; c < NCLS; c++)
        d_xin[(b * NCLS + c) * T_ + t0 + tid] = s[tid][c];
}

// ------------------------- K1: gdot ----------------------------------------
__global__ void __launch_bounds__(384) k_gdot(const float* __restrict__ g_style,
                                              const float* __restrict__ w1) {
    __shared__ float gs[NSTY];
    const int b = blockIdx.x, tid = threadIdx.x;
    for (int c = tid; c < NSTY; c += 384) gs[c] = g_style[b * NSTY + c];
    __syncthreads();
    const int o = tid / 3, k = tid % 3;
    const float* wp = w1 + o * (CIN1W * 3) + NCLS * 3 + k;
    float acc = 0.f;
#pragma unroll 8
    for (int c = 0; c < NSTY; c++) acc = fmaf(gs[c], wp[c * 3], acc);
    d_gdot[b * 3 * C1 + k * C1 + o] = acc;
}

// ------------------------- K2: sdot ----------------------------------------
__global__ void __launch_bounds__(384) k_sdot(const float* __restrict__ char_style,
                                              const float* __restrict__ w1) {
    __shared__ float cs[NCS];
    const int ch = blockIdx.x, b = blockIdx.y, tid = threadIdx.x;
    for (int c = tid; c < NCS; c += 384)
        cs[c] = char_style[((size_t)b * NCLS + ch) * NCS + c];
    __syncthreads();
    const int o = tid / 3, k = tid % 3;
    const float* wp = w1 + o * (CIN1W * 3) + (NCLS + NSTY) * 3 + k;
    float acc = 0.f;
#pragma unroll 8
    for (int c = 0; c < NCS; c++) acc = fmaf(cs[c], wp[c * 3], acc);
    d_sdot[((size_t)b * NCLS + ch) * 3 * C1 + k * C1 + o] = acc;
}

// ------------------------- conv stage --------------------------------------
// Block 256, tile BT=128 t x BO o. Thread: 8t x OT o. CC=8 chunks, dbl-buffer.
template <int STAGE>
__global__ void __launch_bounds__(256)
k_conv(const float* __restrict__ w, const float* __restrict__ bias,
       const float* __restrict__ gns, const float* __restrict__ gnb) {
    constexpr int  CIN  = (STAGE == 1) ? NCLS : (STAGE == 2) ? C1 : C2;
    constexpr int  COUT = (STAGE == 1) ? C1   : (STAGE == 2) ? C2 : C3;
    constexpr int  CINW = (STAGE == 1) ? CIN1W : CIN;
    constexpr bool IS1  = (STAGE == 1);
    constexpr int  BT = 128;
    constexpr int  BO = (COUT >= 64) ? 64 : COUT;
    constexpr int  OT = BO / 16;         // 4 / 4 / 2
    constexpr int  CC = 8;
    constexpr int  NCH = CIN / CC;       // 10 / 16 / 8

    const float* xin = IS1 ? d_xin : (STAGE == 2 ? d_y1 : d_y2);
    float*       y   = IS1 ? d_y1  : (STAGE == 2 ? d_y2 : d_y3);
    const float* mean = (STAGE == 2) ? d_mean1 : d_mean2;
    const float* rstd = (STAGE == 2) ? d_rstd1 : d_rstd2;

    const int b  = blockIdx.z;
    const int t0 = blockIdx.x * BT;
    const int o0 = blockIdx.y * BO;
    const int tid = threadIdx.x;
    const int tx = tid & 15;    // t group (8 t's)
    const int ty = tid >> 4;    // o group (OT o's)

    // xs[p]  = x[t0-1+p], p in [0, BT+2)
    // xsh[p] = x[t0+p]   (shifted copy -> odd pairs are 16B-aligned)
    __shared__ float xs [2][CC][BT + 8];     // 8.5 KB
    __shared__ float xsh[2][CC][BT + 8];     // 8.5 KB
    __shared__ u64   wsd[2][CC][BO * 3];     // duplicated (w,w): 24 KB
    __shared__ float sb[BO];
    __shared__ float gA[CIN], gB[CIN];
    __shared__ float sg[3 * BO];
    __shared__ int   sam[BT + 2];

    if constexpr (!IS1) {
        constexpr int CPG = CIN / 32;
        for (int c = tid; c < CIN; c += 256) {
            const int g = c / CPG;
            const float a = rstd[b * 32 + g] * gns[c];
            gA[c] = a;
            gB[c] = gnb[c] - mean[b * 32 + g] * a;
        }
    }
    if (tid < BO) sb[tid] = bias[o0 + tid];
    if constexpr (IS1) {
        for (int i = tid; i < 3 * BO; i += 256) {
            const int k = i / BO, o = i - k * BO;
            sg[i] = d_gdot[b * 3 * C1 + k * C1 + o0 + o];
        }
        for (int p = tid; p < BT + 2; p += 256) {
            const int t = t0 - 1 + p;
            sam[p] = (t >= 0 && t < T_) ? d_amax[b * T_ + t] : 0;
        }
    }
    __syncthreads();

    auto stage = [&](int ch, int buf) {
        const int c0 = ch * CC;
        for (int i = tid; i < CC * (BT + 2); i += 256) {
            const int cc = i / (BT + 2), p = i - cc * (BT + 2);
            const int t = t0 - 1 + p;
            const int c = c0 + cc;
            float v = 0.f;
            if (t >= 0 && t < T_) {
                v = xin[(b * CIN + c) * T_ + t];
                if constexpr (!IS1) v = fmaxf(fmaf(v, gA[c], gB[c]), 0.f);
            }
            xs[buf][cc][p] = v;
            if (p >= 1) xsh[buf][cc][p - 1] = v;
        }
        for (int i = tid; i < CC * BO * 3; i += 256) {
            const int cc = i / (BO * 3), r = i - cc * (BO * 3);
            const float v = w[(o0 + r / 3) * (CINW * 3) + (c0 + cc) * 3 + (r % 3)];
            wsd[buf][cc][r] = pk2(v, v);
        }
    };

    u64 acc2[OT][4];
#pragma unroll
    for (int j = 0; j < OT; j++)
#pragma unroll
        for (int i = 0; i < 4; i++) acc2[j][i] = 0ull;

    stage(0, 0);
    __syncthreads();

    for (int ch = 0; ch < NCH; ch++) {
        const int buf = ch & 1;
        if (ch + 1 < NCH) stage(ch + 1, buf ^ 1);

#pragma unroll
        for (int cc = 0; cc < CC; cc++) {
            // even pairs: 2x LDS.128 + 1x LDS.64, odd pairs: 2x LDS.128
            const ulonglong2* xe =
                reinterpret_cast<const ulonglong2*>(&xs[buf][cc][tx * 8]);
            const ulonglong2* xo =
                reinterpret_cast<const ulonglong2*>(&xsh[buf][cc][tx * 8]);
            const ulonglong2 e01 = xe[0], e23 = xe[1];
            const u64 pe4 =
                *reinterpret_cast<const u64*>(&xs[buf][cc][tx * 8 + 8]);
            const ulonglong2 q01 = xo[0], q23 = xo[1];
            const u64 pe[5] = {e01.x, e01.y, e23.x, e23.y, pe4};
            const u64 po[4] = {q01.x, q01.y, q23.x, q23.y};

            // weights: OT*3 duplicated u64s, 16B-aligned -> (OT*3)/2 LDS.128
            const ulonglong2* wv = reinterpret_cast<const ulonglong2*>(
                &wsd[buf][cc][ty * (OT * 3)]);
            u64 W[OT * 3];
#pragma unroll
            for (int q = 0; q < (OT * 3) / 2; q++) {
                const ulonglong2 t2 = wv[q];
                W[2 * q] = t2.x; W[2 * q + 1] = t2.y;
            }

#pragma unroll
            for (int j = 0; j < OT; j++) {
#pragma unroll
                for (int i = 0; i < 4; i++) {
                    ffma2(acc2[j][i], W[j * 3 + 0], pe[i]);
                    ffma2(acc2[j][i], W[j * 3 + 1], po[i]);
                    ffma2(acc2[j][i], W[j * 3 + 2], pe[i + 1]);
                }
            }
        }
        __syncthreads();
    }

    // ------------------------- epilogue ------------------------------------
    float ov[OT][8];
#pragma unroll
    for (int j = 0; j < OT; j++)
#pragma unroll
        for (int i = 0; i < 4; i++)
            upk2(ov[j][2 * i], ov[j][2 * i + 1], acc2[j][i]);

    if constexpr (IS1) {
        const float4* sd4 = reinterpret_cast<const float4*>(
            d_sdot + (size_t)b * NCLS * 3 * C1);
        const int oq = (o0 >> 2) + ty;
#pragma unroll
        for (int i = 0; i < 8; i++) {
            const int tl = tx * 8 + i;
            const int t = t0 + tl;
            float4 s1 = sd4[(size_t)(sam[tl + 1] * 3 + 1) * 32 + oq];
            ov[0][i] += s1.x + sg[BO + ty * 4 + 0];
            ov[1][i] += s1.y + sg[BO + ty * 4 + 1];
            ov[2][i] += s1.z + sg[BO + ty * 4 + 2];
            ov[3][i] += s1.w + sg[BO + ty * 4 + 3];
            if (t > 0) {
                float4 s0 = sd4[(size_t)(sam[tl] * 3 + 0) * 32 + oq];
                ov[0][i] += s0.x + sg[ty * 4 + 0];
                ov[1][i] += s0.y + sg[ty * 4 + 1];
                ov[2][i] += s0.z + sg[ty * 4 + 2];
                ov[3][i] += s0.w + sg[ty * 4 + 3];
            }
            if (t < T_ - 1) {
                float4 s2 = sd4[(size_t)(sam[tl + 2] * 3 + 2) * 32 + oq];
                ov[0][i] += s2.x + sg[2 * BO + ty * 4 + 0];
                ov[1][i] += s2.y + sg[2 * BO + ty * 4 + 1];
                ov[2][i] += s2.z + sg[2 * BO + ty * 4 + 2];
                ov[3][i] += s2.w + sg[2 * BO + ty * 4 + 3];
            }
        }
    }

#pragma unroll
    for (int j = 0; j < OT; j++) {
        const int ol = ty * OT + j;
        const float bo = sb[ol];
        float4* yp = reinterpret_cast<float4*>(
            y + (size_t)(b * COUT + o0 + ol) * T_ + t0 + tx * 8);
        yp[0] = make_float4(ov[j][0] + bo, ov[j][1] + bo, ov[j][2] + bo, ov[j][3] + bo);
        yp[1] = make_float4(ov[j][4] + bo, ov[j][5] + bo, ov[j][6] + bo, ov[j][7] + bo);
    }
}

// ------------------------- GN stats ----------------------------------------
template <int STAGE>
__global__ void __launch_bounds__(256) k_gnstats() {
    constexpr int C   = (STAGE == 1) ? C1 : (STAGE == 2) ? C2 : C3;
    constexpr int CPG = C / 32;
    constexpr int N   = CPG * T_;
    const float* yv  = (STAGE == 1) ? d_y1 : (STAGE == 2) ? d_y2 : d_y3;
    float* meanp = (STAGE == 1) ? d_mean1 : (STAGE == 2) ? d_mean2 : d_mean3;
    float* rstdp = (STAGE == 1) ? d_rstd1 : (STAGE == 2) ? d_rstd2 : d_rstd3;

    const int bg = blockIdx.x;
    const float4* p = reinterpret_cast<const float4*>(
        yv + (size_t)(bg / 32) * C * T_ + (size_t)(bg % 32) * CPG * T_);
    float s = 0.f, s2 = 0.f;
    for (int i = threadIdx.x; i < N / 4; i += 256) {
        const float4 v = p[i];
        s += v.x + v.y + v.z + v.w;
        s2 = fmaf(v.x, v.x, fmaf(v.y, v.y, fmaf(v.z, v.z, fmaf(v.w, v.w, s2))));
    }
    __shared__ float ss[8], ss2[8];
#pragma unroll
    for (int o = 16; o; o >>= 1) {
        s  += __shfl_down_sync(0xffffffffu, s,  o);
        s2 += __shfl_down_sync(0xffffffffu, s2, o);
    }
    if ((threadIdx.x & 31) == 0) { ss[threadIdx.x >> 5] = s; ss2[threadIdx.x >> 5] = s2; }
    __syncthreads();
    if (threadIdx.x == 0) {
        float S = 0.f, S2 = 0.f;
#pragma unroll
        for (int i = 0; i < 8; i++) { S += ss[i]; S2 += ss2[i]; }
        const float m = S / N;
        const float var = S2 / N - m * m;
        meanp[bg] = m;
        rstdp[bg] = rsqrtf(var + 1e-5f);
    }
}

// ------------------------- conv4 (k=1) + output affine ---------------------
__global__ void __launch_bounds__(256)
k_out(const float* __restrict__ w4, const float* __restrict__ b4,
      const float* __restrict__ s3, const float* __restrict__ bb3,
      const float* __restrict__ omean, const float* __restrict__ ostd,
      float* __restrict__ out) {
    const int b = blockIdx.y;
    const int t = blockIdx.x * 256 + threadIdx.x;
    __shared__ float A[32], Bc[32], W[32];
    if (threadIdx.x < 32) {
        const int c = threadIdx.x;
        const float a = d_rstd3[b * 32 + c] * s3[c];
        A[c] = a;
        Bc[c] = bb3[c] - d_mean3[b * 32 + c] * a;
        W[c] = w4[c];
    }
    __syncthreads();
    float acc = b4[0];
#pragma unroll
    for (int c = 0; c < 32; c++) {
        float v = d_y3[(b * 32 + c) * T_ + t];
        v = fmaxf(fmaf(v, A[c], Bc[c]), 0.f);
        acc = fmaf(W[c], v, acc);
    }
    out[(size_t)t * NB + b] = fmaf(acc, ostd[0], omean[0]);
}

// ------------------------- launch ------------------------------------------
extern "C" void kernel_launch(void* const* d_in, const int* in_sizes, int n_in,
                              void* d_out, int out_size) {
    const float* input      = (const float*)d_in[0];
    const float* g_style    = (const float*)d_in[1];
    const float* char_style = (const float*)d_in[3];
    const float* c1w = (const float*)d_in[4];
    const float* c1b = (const float*)d_in[5];
    const float* g1s = (const float*)d_in[6];
    const float* g1b = (const float*)d_in[7];
    const float* c2w = (const float*)d_in[8];
    const float* c2b = (const float*)d_in[9];
    const float* g2s = (const float*)d_in[10];
    const float* g2b = (const float*)d_in[11];
    const float* c3w = (const float*)d_in[12];
    const float* c3b = (const float*)d_in[13];
    const float* g3s = (const float*)d_in[14];
    const float* g3b = (const float*)d_in[15];
    const float* c4w = (const float*)d_in[16];
    const float* c4b = (const float*)d_in[17];
    const float* om  = (const float*)d_in[18];
    const float* os  = (const float*)d_in[19];
    float* out = (float*)d_out;

    k_prep<<<dim3(T_ / 128, NB), 128>>>(input);
    k_gdot<<<NB, 384>>>(g_style, c1w);
    k_sdot<<<dim3(NCLS, NB), 384>>>(char_style, c1w);

    k_conv<1><<<dim3(T_ / 128, C1 / 64, NB), 256>>>(c1w, c1b, nullptr, nullptr);
    k_gnstats<1><<<NB * 32, 256>>>();

    k_conv<2><<<dim3(T_ / 128, 1, NB), 256>>>(c2w, c2b, g1s, g1b);
    k_gnstats<2><<<NB * 32, 256>>>();

    k_conv<3><<<dim3(T_ / 128, 1, NB), 256>>>(c3w, c3b, g2s, g2b);
    k_gnstats<3><<<NB * 32, 256>>>();

    k_out<<<dim3(T_ / 256, NB), 256>>>(c4w, c4b, g3s, g3b, om, os, out);
}

// round 8
// speedup vs baseline: 1.1649x; 1.1649x over previous
#include <cuda_runtime.h>
#include <cstdint>

// ---------------------------------------------------------------------------
// CharCountCNN — round 8: R5 structure (measured best: 78 regs, 3 blocks/SM)
// + pre-transposed pre-duplicated weights so conv staging is coalesced.
// ---------------------------------------------------------------------------

constexpr int T_   = 1024;
constexpr int NB   = 128;
constexpr int NCLS = 80;
constexpr int NSTY = 256;
constexpr int NCS  = 64;
constexpr int C1   = 128;
constexpr int C2   = 64;
constexpr int C3   = 32;
constexpr int CIN1W = 400;

// ------------------------- scratch -----------------------------------------
__device__ float d_xin [NB * NCLS * T_];
__device__ int   d_amax[NB * T_];
__device__ float d_gdot[NB * 3 * C1];           // [b][k][o]
__device__ float d_sdot[NB * NCLS * 3 * C1];    // [b][ch][k][o]
__device__ float d_y1  [NB * C1 * T_];
__device__ float d_y2  [NB * C2 * T_];
__device__ float d_y3  [NB * C3 * T_];
__device__ float d_mean1[NB * 32], d_rstd1[NB * 32];
__device__ float d_mean2[NB * 32], d_rstd2[NB * 32];
__device__ float d_mean3[NB * 32], d_rstd3[NB * 32];

using u64 = unsigned long long;
// pre-transposed, pre-duplicated weights: [c][o][k] of (w,w) u64
__device__ u64 d_w1d[NCLS * C1 * 3];
__device__ u64 d_w2d[C1 * C2 * 3];
__device__ u64 d_w3d[C2 * C3 * 3];

// ------------------------- f32x2 helpers -----------------------------------
__device__ __forceinline__ u64 pk2(float lo, float hi) {
    u64 r;
    asm("mov.b64 %0, {%1, %2};" : "=l"(r) : "f"(lo), "f"(hi));
    return r;
}
__device__ __forceinline__ void upk2(float& lo, float& hi, u64 v) {
    asm("mov.b64 {%0, %1}, %2;" : "=f"(lo), "=f"(hi) : "l"(v));
}
__device__ __forceinline__ void ffma2(u64& d, u64 a, u64 b) {
    asm("fma.rn.f32x2 %0, %1, %2, %0;" : "+l"(d) : "l"(a), "l"(b));
}

// ------------------------- weight transform --------------------------------
// dst[(c*COUT + o)*3 + k] = dup(w[o*CINW*3 + c*3 + k])
__global__ void __launch_bounds__(256)
k_wdup(const float* __restrict__ w, u64* __restrict__ dst,
       int CINW, int COUT, int total) {
    const int idx = blockIdx.x * 256 + threadIdx.x;
    if (idx >= total) return;
    const int c   = idx / (COUT * 3);
    const int rem = idx - c * (COUT * 3);
    const int o   = rem / 3;
    const int k   = rem - o * 3;
    const float v = w[o * CINW * 3 + c * 3 + k];
    dst[idx] = pk2(v, v);
}

// ------------------------- K0: argmax + transpose --------------------------
__global__ void __launch_bounds__(128) k_prep(const float* __restrict__ inp) {
    __shared__ float s[128][NCLS + 1];
    const int b   = blockIdx.y;
    const int t0  = blockIdx.x * 128;
    const int tid = threadIdx.x;

    const float4* row = reinterpret_cast<const float4*>(
        inp + ((size_t)(t0 + tid) * NB + b) * NCLS);

    float best = -3.4e38f;
    int   bi   = 0;
#pragma unroll
    for (int c4 = 0; c4 < NCLS / 4; c4++) {
        float4 v = row[c4];
        int c = c4 * 4;
        s[tid][c + 0] = v.x; s[tid][c + 1] = v.y;
        s[tid][c + 2] = v.z; s[tid][c + 3] = v.w;
        if (v.x > best) { best = v.x; bi = c + 0; }
        if (v.y > best) { best = v.y; bi = c + 1; }
        if (v.z > best) { best = v.z; bi = c + 2; }
        if (v.w > best) { best = v.w; bi = c + 3; }
    }
    d_amax[b * T_ + t0 + tid] = bi;
    __syncthreads();
#pragma unroll 4
    for (int c = 0; c < NCLS; c++)
        d_xin[(b * NCLS + c) * T_ + t0 + tid] = s[tid][c];
}

// ------------------------- K1: gdot ----------------------------------------
__global__ void __launch_bounds__(384) k_gdot(const float* __restrict__ g_style,
                                              const float* __restrict__ w1) {
    __shared__ float gs[NSTY];
    const int b = blockIdx.x, tid = threadIdx.x;
    for (int c = tid; c < NSTY; c += 384) gs[c] = g_style[b * NSTY + c];
    __syncthreads();
    const int o = tid / 3, k = tid % 3;
    const float* wp = w1 + o * (CIN1W * 3) + NCLS * 3 + k;
    float acc = 0.f;
#pragma unroll 8
    for (int c = 0; c < NSTY; c++) acc = fmaf(gs[c], wp[c * 3], acc);
    d_gdot[b * 3 * C1 + k * C1 + o] = acc;
}

// ------------------------- K2: sdot ----------------------------------------
__global__ void __launch_bounds__(384) k_sdot(const float* __restrict__ char_style,
                                              const float* __restrict__ w1) {
    __shared__ float cs[NCS];
    const int ch = blockIdx.x, b = blockIdx.y, tid = threadIdx.x;
    for (int c = tid; c < NCS; c += 384)
        cs[c] = char_style[((size_t)b * NCLS + ch) * NCS + c];
    __syncthreads();
    const int o = tid / 3, k = tid % 3;
    const float* wp = w1 + o * (CIN1W * 3) + (NCLS + NSTY) * 3 + k;
    float acc = 0.f;
#pragma unroll 8
    for (int c = 0; c < NCS; c++) acc = fmaf(cs[c], wp[c * 3], acc);
    d_sdot[((size_t)b * NCLS + ch) * 3 * C1 + k * C1 + o] = acc;
}

// ------------------------- conv stage (f32x2, dbl-buffer, CC=8) ------------
// Block 256, tile BT=128 t x BO o. Thread: 8t x OT o. Identical inner loop to
// the measured-best R5 kernel; only the weight staging source changed.
template <int STAGE>
__global__ void __launch_bounds__(256)
k_conv(const float* __restrict__ bias,
       const float* __restrict__ gns, const float* __restrict__ gnb) {
    constexpr int  CIN  = (STAGE == 1) ? NCLS : (STAGE == 2) ? C1 : C2;
    constexpr int  COUT = (STAGE == 1) ? C1   : (STAGE == 2) ? C2 : C3;
    constexpr bool IS1  = (STAGE == 1);
    constexpr int  BT = 128;
    constexpr int  BO = (COUT >= 64) ? 64 : COUT;
    constexpr int  OT = BO / 16;         // 4 / 4 / 2
    constexpr int  CC = 8;
    constexpr int  NCH = CIN / CC;       // 10 / 16 / 8

    const float* xin = IS1 ? d_xin : (STAGE == 2 ? d_y1 : d_y2);
    float*       y   = IS1 ? d_y1  : (STAGE == 2 ? d_y2 : d_y3);
    const u64*   wsrc = IS1 ? d_w1d : (STAGE == 2 ? d_w2d : d_w3d);
    const float* mean = (STAGE == 2) ? d_mean1 : d_mean2;
    const float* rstd = (STAGE == 2) ? d_rstd1 : d_rstd2;

    const int b  = blockIdx.z;
    const int t0 = blockIdx.x * BT;
    const int o0 = blockIdx.y * BO;
    const int tid = threadIdx.x;
    const int tx = tid & 15;    // t group (8 t's)
    const int ty = tid >> 4;    // o group (OT o's)

    __shared__ float xs [2][CC][BT + 8];     // 8.5 KB
    __shared__ u64   wsd[2][CC][BO * 3];     // duplicated (w,w): 24 KB
    __shared__ float sb[BO];
    __shared__ float gA[CIN], gB[CIN];
    __shared__ float sg[3 * BO];
    __shared__ int   sam[BT + 2];

    if constexpr (!IS1) {
        constexpr int CPG = CIN / 32;
        for (int c = tid; c < CIN; c += 256) {
            const int g = c / CPG;
            const float a = rstd[b * 32 + g] * gns[c];
            gA[c] = a;
            gB[c] = gnb[c] - mean[b * 32 + g] * a;
        }
    }
    if (tid < BO) sb[tid] = bias[o0 + tid];
    if constexpr (IS1) {
        for (int i = tid; i < 3 * BO; i += 256) {
            const int k = i / BO, o = i - k * BO;
            sg[i] = d_gdot[b * 3 * C1 + k * C1 + o0 + o];
        }
        for (int p = tid; p < BT + 2; p += 256) {
            const int t = t0 - 1 + p;
            sam[p] = (t >= 0 && t < T_) ? d_amax[b * T_ + t] : 0;
        }
    }
    __syncthreads();

    auto stage = [&](int ch, int buf) {
        const int c0 = ch * CC;
        for (int i = tid; i < CC * (BT + 2); i += 256) {
            const int cc = i / (BT + 2), p = i - cc * (BT + 2);
            const int t = t0 - 1 + p;
            const int c = c0 + cc;
            float v = 0.f;
            if (t >= 0 && t < T_) {
                v = xin[(b * CIN + c) * T_ + t];
                if constexpr (!IS1) v = fmaxf(fmaf(v, gA[c], gB[c]), 0.f);
            }
            xs[buf][cc][p] = v;
        }
        // coalesced: consecutive i -> consecutive u64 in d_wNd
        for (int i = tid; i < CC * BO * 3; i += 256) {
            const int cc = i / (BO * 3), r = i - cc * (BO * 3);
            wsd[buf][cc][r] = wsrc[(size_t)(c0 + cc) * (COUT * 3) + o0 * 3 + r];
        }
    };

    u64 acc2[OT][4];
#pragma unroll
    for (int j = 0; j < OT; j++)
#pragma unroll
        for (int i = 0; i < 4; i++) acc2[j][i] = 0ull;

    stage(0, 0);
    __syncthreads();

    for (int ch = 0; ch < NCH; ch++) {
        const int buf = ch & 1;
        if (ch + 1 < NCH) stage(ch + 1, buf ^ 1);   // overlap with compute

#pragma unroll
        for (int cc = 0; cc < CC; cc++) {
            const float4* xp = reinterpret_cast<const float4*>(&xs[buf][cc][tx * 8]);
            const float4 a0 = xp[0], a1 = xp[1], a2 = xp[2];
            u64 pe[5], po[4];
            pe[0] = pk2(a0.x, a0.y); pe[1] = pk2(a0.z, a0.w);
            pe[2] = pk2(a1.x, a1.y); pe[3] = pk2(a1.z, a1.w);
            pe[4] = pk2(a2.x, a2.y);
            po[0] = pk2(a0.y, a0.z); po[1] = pk2(a0.w, a1.x);
            po[2] = pk2(a1.y, a1.z); po[3] = pk2(a1.w, a2.x);

            const u64* wrow = &wsd[buf][cc][0];
#pragma unroll
            for (int j = 0; j < OT; j++) {
                const int ol = ty * OT + j;
                const u64 w0 = wrow[ol * 3 + 0];
                const u64 w1v = wrow[ol * 3 + 1];
                const u64 w2 = wrow[ol * 3 + 2];
#pragma unroll
                for (int i = 0; i < 4; i++) {
                    ffma2(acc2[j][i], w0, pe[i]);
                    ffma2(acc2[j][i], w1v, po[i]);
                    ffma2(acc2[j][i], w2, pe[i + 1]);
                }
            }
        }
        __syncthreads();   // one barrier per chunk
    }

    // ------------------------- epilogue ------------------------------------
    float ov[OT][8];
#pragma unroll
    for (int j = 0; j < OT; j++)
#pragma unroll
        for (int i = 0; i < 4; i++)
            upk2(ov[j][2 * i], ov[j][2 * i + 1], acc2[j][i]);

    if constexpr (IS1) {
        const float4* sd4 = reinterpret_cast<const float4*>(
            d_sdot + (size_t)b * NCLS * 3 * C1);
        const int oq = (o0 >> 2) + ty;
#pragma unroll
        for (int i = 0; i < 8; i++) {
            const int tl = tx * 8 + i;
            const int t = t0 + tl;
            float4 s1 = sd4[(size_t)(sam[tl + 1] * 3 + 1) * 32 + oq];
            ov[0][i] += s1.x + sg[BO + ty * 4 + 0];
            ov[1][i] += s1.y + sg[BO + ty * 4 + 1];
            ov[2][i] += s1.z + sg[BO + ty * 4 + 2];
            ov[3][i] += s1.w + sg[BO + ty * 4 + 3];
            if (t > 0) {
                float4 s0 = sd4[(size_t)(sam[tl] * 3 + 0) * 32 + oq];
                ov[0][i] += s0.x + sg[ty * 4 + 0];
                ov[1][i] += s0.y + sg[ty * 4 + 1];
                ov[2][i] += s0.z + sg[ty * 4 + 2];
                ov[3][i] += s0.w + sg[ty * 4 + 3];
            }
            if (t < T_ - 1) {
                float4 s2 = sd4[(size_t)(sam[tl + 2] * 3 + 2) * 32 + oq];
                ov[0][i] += s2.x + sg[2 * BO + ty * 4 + 0];
                ov[1][i] += s2.y + sg[2 * BO + ty * 4 + 1];
                ov[2][i] += s2.z + sg[2 * BO + ty * 4 + 2];
                ov[3][i] += s2.w + sg[2 * BO + ty * 4 + 3];
            }
        }
    }

#pragma unroll
    for (int j = 0; j < OT; j++) {
        const int ol = ty * OT + j;
        const float bo = sb[ol];
        float4* yp = reinterpret_cast<float4*>(
            y + (size_t)(b * COUT + o0 + ol) * T_ + t0 + tx * 8);
        yp[0] = make_float4(ov[j][0] + bo, ov[j][1] + bo, ov[j][2] + bo, ov[j][3] + bo);
        yp[1] = make_float4(ov[j][4] + bo, ov[j][5] + bo, ov[j][6] + bo, ov[j][7] + bo);
    }
}

// ------------------------- GN stats ----------------------------------------
template <int STAGE>
__global__ void __launch_bounds__(256) k_gnstats() {
    constexpr int C   = (STAGE == 1) ? C1 : (STAGE == 2) ? C2 : C3;
    constexpr int CPG = C / 32;
    constexpr int N   = CPG * T_;
    const float* yv  = (STAGE == 1) ? d_y1 : (STAGE == 2) ? d_y2 : d_y3;
    float* meanp = (STAGE == 1) ? d_mean1 : (STAGE == 2) ? d_mean2 : d_mean3;
    float* rstdp = (STAGE == 1) ? d_rstd1 : (STAGE == 2) ? d_rstd2 : d_rstd3;

    const int bg = blockIdx.x;
    const float4* p = reinterpret_cast<const float4*>(
        yv + (size_t)(bg / 32) * C * T_ + (size_t)(bg % 32) * CPG * T_);
    float s = 0.f, s2 = 0.f;
    for (int i = threadIdx.x; i < N / 4; i += 256) {
        const float4 v = p[i];
        s += v.x + v.y + v.z + v.w;
        s2 = fmaf(v.x, v.x, fmaf(v.y, v.y, fmaf(v.z, v.z, fmaf(v.w, v.w, s2))));
    }
    __shared__ float ss[8], ss2[8];
#pragma unroll
    for (int o = 16; o; o >>= 1) {
        s  += __shfl_down_sync(0xffffffffu, s,  o);
        s2 += __shfl_down_sync(0xffffffffu, s2, o);
    }
    if ((threadIdx.x & 31) == 0) { ss[threadIdx.x >> 5] = s; ss2[threadIdx.x >> 5] = s2; }
    __syncthreads();
    if (threadIdx.x == 0) {
        float S = 0.f, S2 = 0.f;
#pragma unroll
        for (int i = 0; i < 8; i++) { S += ss[i]; S2 += ss2[i]; }
        const float m = S / N;
        const float var = S2 / N - m * m;
        meanp[bg] = m;
        rstdp[bg] = rsqrtf(var + 1e-5f);
    }
}

// ------------------------- conv4 (k=1) + output affine ---------------------
__global__ void __launch_bounds__(256)
k_out(const float* __restrict__ w4, const float* __restrict__ b4,
      const float* __restrict__ s3, const float* __restrict__ bb3,
      const float* __restrict__ omean, const float* __restrict__ ostd,
      float* __restrict__ out) {
    const int b = blockIdx.y;
    const int t = blockIdx.x * 256 + threadIdx.x;
    __shared__ float A[32], Bc[32], W[32];
    if (threadIdx.x < 32) {
        const int c = threadIdx.x;
        const float a = d_rstd3[b * 32 + c] * s3[c];
        A[c] = a;
        Bc[c] = bb3[c] - d_mean3[b * 32 + c] * a;
        W[c] = w4[c];
    }
    __syncthreads();
    float acc = b4[0];
#pragma unroll
    for (int c = 0; c < 32; c++) {
        float v = d_y3[(b * 32 + c) * T_ + t];
        v = fmaxf(fmaf(v, A[c], Bc[c]), 0.f);
        acc = fmaf(W[c], v, acc);
    }
    out[(size_t)t * NB + b] = fmaf(acc, ostd[0], omean[0]);
}

// ------------------------- launch ------------------------------------------
extern "C" void kernel_launch(void* const* d_in, const int* in_sizes, int n_in,
                              void* d_out, int out_size) {
    const float* input      = (const float*)d_in[0];
    const float* g_style    = (const float*)d_in[1];
    const float* char_style = (const float*)d_in[3];
    const float* c1w = (const float*)d_in[4];
    const float* c1b = (const float*)d_in[5];
    const float* g1s = (const float*)d_in[6];
    const float* g1b = (const float*)d_in[7];
    const float* c2w = (const float*)d_in[8];
    const float* c2b = (const float*)d_in[9];
    const float* g2s = (const float*)d_in[10];
    const float* g2b = (const float*)d_in[11];
    const float* c3w = (const float*)d_in[12];
    const float* c3b = (const float*)d_in[13];
    const float* g3s = (const float*)d_in[14];
    const float* g3b = (const float*)d_in[15];
    const float* c4w = (const float*)d_in[16];
    const float* c4b = (const float*)d_in[17];
    const float* om  = (const float*)d_in[18];
    const float* os  = (const float*)d_in[19];
    float* out = (float*)d_out;

    // weight transforms (tiny, once per launch)
    u64 *w1d, *w2d, *w3d;
    cudaGetSymbolAddress((void**)&w1d, d_w1d);
    cudaGetSymbolAddress((void**)&w2d, d_w2d);
    cudaGetSymbolAddress((void**)&w3d, d_w3d);
    k_wdup<<<(NCLS * C1 * 3 + 255) / 256, 256>>>(c1w, w1d, CIN1W, C1, NCLS * C1 * 3);
    k_wdup<<<(C1 * C2 * 3 + 255) / 256, 256>>>(c2w, w2d, C1, C2, C1 * C2 * 3);
    k_wdup<<<(C2 * C3 * 3 + 255) / 256, 256>>>(c3w, w3d, C2, C3, C2 * C3 * 3);

    k_prep<<<dim3(T_ / 128, NB), 128>>>(input);
    k_gdot<<<NB, 384>>>(g_style, c1w);
    k_sdot<<<dim3(NCLS, NB), 384>>>(char_style, c1w);

    k_conv<1><<<dim3(T_ / 128, C1 / 64, NB), 256>>>(c1b, nullptr, nullptr);
    k_gnstats<1><<<NB * 32, 256>>>();

    k_conv<2><<<dim3(T_ / 128, 1, NB), 256>>>(c2b, g1s, g1b);
    k_gnstats<2><<<NB * 32, 256>>>();

    k_conv<3><<<dim3(T_ / 128, 1, NB), 256>>>(c3b, g2s, g2b);
    k_gnstats<3><<<NB * 32, 256>>>();

    k_out<<<dim3(T_ / 256, NB), 256>>>(c4w, c4b, g3s, g3b, om, os, out);
}

// round 9
// speedup vs baseline: 1.1650x; 1.0001x over previous
#include <cuda_runtime.h>
#include <cstdint>

// ---------------------------------------------------------------------------
// CharCountCNN — round 8: R5 structure (measured best: 78 regs, 3 blocks/SM)
// + pre-transposed pre-duplicated weights so conv staging is coalesced.
// ---------------------------------------------------------------------------

constexpr int T_   = 1024;
constexpr int NB   = 128;
constexpr int NCLS = 80;
constexpr int NSTY = 256;
constexpr int NCS  = 64;
constexpr int C1   = 128;
constexpr int C2   = 64;
constexpr int C3   = 32;
constexpr int CIN1W = 400;

// ------------------------- scratch -----------------------------------------
__device__ float d_xin [NB * NCLS * T_];
__device__ int   d_amax[NB * T_];
__device__ float d_gdot[NB * 3 * C1];           // [b][k][o]
__device__ float d_sdot[NB * NCLS * 3 * C1];    // [b][ch][k][o]
__device__ float d_y1  [NB * C1 * T_];
__device__ float d_y2  [NB * C2 * T_];
__device__ float d_y3  [NB * C3 * T_];
__device__ float d_mean1[NB * 32], d_rstd1[NB * 32];
__device__ float d_mean2[NB * 32], d_rstd2[NB * 32];
__device__ float d_mean3[NB * 32], d_rstd3[NB * 32];

using u64 = unsigned long long;
// pre-transposed, pre-duplicated weights: [c][o][k] of (w,w) u64
__device__ u64 d_w1d[NCLS * C1 * 3];
__device__ u64 d_w2d[C1 * C2 * 3];
__device__ u64 d_w3d[C2 * C3 * 3];

// ------------------------- f32x2 helpers -----------------------------------
__device__ __forceinline__ u64 pk2(float lo, float hi) {
    u64 r;
    asm("mov.b64 %0, {%1, %2};" : "=l"(r) : "f"(lo), "f"(hi));
    return r;
}
__device__ __forceinline__ void upk2(float& lo, float& hi, u64 v) {
    asm("mov.b64 {%0, %1}, %2;" : "=f"(lo), "=f"(hi) : "l"(v));
}
__device__ __forceinline__ void ffma2(u64& d, u64 a, u64 b) {
    asm("fma.rn.f32x2 %0, %1, %2, %0;" : "+l"(d) : "l"(a), "l"(b));
}

// ------------------------- weight transform --------------------------------
// dst[(c*COUT + o)*3 + k] = dup(w[o*CINW*3 + c*3 + k])
__global__ void __launch_bounds__(256)
k_wdup(const float* __restrict__ w, u64* __restrict__ dst,
       int CINW, int COUT, int total) {
    const int idx = blockIdx.x * 256 + threadIdx.x;
    if (idx >= total) return;
    const int c   = idx / (COUT * 3);
    const int rem = idx - c * (COUT * 3);
    const int o   = rem / 3;
    const int k   = rem - o * 3;
    const float v = w[o * CINW * 3 + c * 3 + k];
    dst[idx] = pk2(v, v);
}

// ------------------------- K0: argmax + transpose --------------------------
__global__ void __launch_bounds__(128) k_prep(const float* __restrict__ inp) {
    __shared__ float s[128][NCLS + 1];
    const int b   = blockIdx.y;
    const int t0  = blockIdx.x * 128;
    const int tid = threadIdx.x;

    const float4* row = reinterpret_cast<const float4*>(
        inp + ((size_t)(t0 + tid) * NB + b) * NCLS);

    float best = -3.4e38f;
    int   bi   = 0;
#pragma unroll
    for (int c4 = 0; c4 < NCLS / 4; c4++) {
        float4 v = row[c4];
        int c = c4 * 4;
        s[tid][c + 0] = v.x; s[tid][c + 1] = v.y;
        s[tid][c + 2] = v.z; s[tid][c + 3] = v.w;
        if (v.x > best) { best = v.x; bi = c + 0; }
        if (v.y > best) { best = v.y; bi = c + 1; }
        if (v.z > best) { best = v.z; bi = c + 2; }
        if (v.w > best) { best = v.w; bi = c + 3; }
    }
    d_amax[b * T_ + t0 + tid] = bi;
    __syncthreads();
#pragma unroll 4
    for (int c = 0; c < NCLS; c++)
        d_xin[(b * NCLS + c) * T_ + t0 + tid] = s[tid][c];
}

// ------------------------- K1: gdot ----------------------------------------
__global__ void __launch_bounds__(384) k_gdot(const float* __restrict__ g_style,
                                              const float* __restrict__ w1) {
    __shared__ float gs[NSTY];
    const int b = blockIdx.x, tid = threadIdx.x;
    for (int c = tid; c < NSTY; c += 384) gs[c] = g_style[b * NSTY + c];
    __syncthreads();
    const int o = tid / 3, k = tid % 3;
    const float* wp = w1 + o * (CIN1W * 3) + NCLS * 3 + k;
    float acc = 0.f;
#pragma unroll 8
    for (int c = 0; c < NSTY; c++) acc = fmaf(gs[c], wp[c * 3], acc);
    d_gdot[b * 3 * C1 + k * C1 + o] = acc;
}

// ------------------------- K2: sdot ----------------------------------------
__global__ void __launch_bounds__(384) k_sdot(const float* __restrict__ char_style,
                                              const float* __restrict__ w1) {
    __shared__ float cs[NCS];
    const int ch = blockIdx.x, b = blockIdx.y, tid = threadIdx.x;
    for (int c = tid; c < NCS; c += 384)
        cs[c] = char_style[((size_t)b * NCLS + ch) * NCS + c];
    __syncthreads();
    const int o = tid / 3, k = tid % 3;
    const float* wp = w1 + o * (CIN1W * 3) + (NCLS + NSTY) * 3 + k;
    float acc = 0.f;
#pragma unroll 8
    for (int c = 0; c < NCS; c++) acc = fmaf(cs[c], wp[c * 3], acc);
    d_sdot[((size_t)b * NCLS + ch) * 3 * C1 + k * C1 + o] = acc;
}

// ------------------------- conv stage (f32x2, dbl-buffer, CC=8) ------------
// Block 256, tile BT=128 t x BO o. Thread: 8t x OT o. Identical inner loop to
// the measured-best R5 kernel; only the weight staging source changed.
template <int STAGE>
__global__ void __launch_bounds__(256)
k_conv(const float* __restrict__ bias,
       const float* __restrict__ gns, const float* __restrict__ gnb) {
    constexpr int  CIN  = (STAGE == 1) ? NCLS : (STAGE == 2) ? C1 : C2;
    constexpr int  COUT = (STAGE == 1) ? C1   : (STAGE == 2) ? C2 : C3;
    constexpr bool IS1  = (STAGE == 1);
    constexpr int  BT = 128;
    constexpr int  BO = (COUT >= 64) ? 64 : COUT;
    constexpr int  OT = BO / 16;         // 4 / 4 / 2
    constexpr int  CC = 8;
    constexpr int  NCH = CIN / CC;       // 10 / 16 / 8

    const float* xin = IS1 ? d_xin : (STAGE == 2 ? d_y1 : d_y2);
    float*       y   = IS1 ? d_y1  : (STAGE == 2 ? d_y2 : d_y3);
    const u64*   wsrc = IS1 ? d_w1d : (STAGE == 2 ? d_w2d : d_w3d);
    const float* mean = (STAGE == 2) ? d_mean1 : d_mean2;
    const float* rstd = (STAGE == 2) ? d_rstd1 : d_rstd2;

    const int b  = blockIdx.z;
    const int t0 = blockIdx.x * BT;
    const int o0 = blockIdx.y * BO;
    const int tid = threadIdx.x;
    const int tx = tid & 15;    // t group (8 t's)
    const int ty = tid >> 4;    // o group (OT o's)

    __shared__ float xs [2][CC][BT + 8];     // 8.5 KB
    __shared__ u64   wsd[2][CC][BO * 3];     // duplicated (w,w): 24 KB
    __shared__ float sb[BO];
    __shared__ float gA[CIN], gB[CIN];
    __shared__ float sg[3 * BO];
    __shared__ int   sam[BT + 2];

    if constexpr (!IS1) {
        constexpr int CPG = CIN / 32;
        for (int c = tid; c < CIN; c += 256) {
            const int g = c / CPG;
            const float a = rstd[b * 32 + g] * gns[c];
            gA[c] = a;
            gB[c] = gnb[c] - mean[b * 32 + g] * a;
        }
    }
    if (tid < BO) sb[tid] = bias[o0 + tid];
    if constexpr (IS1) {
        for (int i = tid; i < 3 * BO; i += 256) {
            const int k = i / BO, o = i - k * BO;
            sg[i] = d_gdot[b * 3 * C1 + k * C1 + o0 + o];
        }
        for (int p = tid; p < BT + 2; p += 256) {
            const int t = t0 - 1 + p;
            sam[p] = (t >= 0 && t < T_) ? d_amax[b * T_ + t] : 0;
        }
    }
    __syncthreads();

    auto stage = [&](int ch, int buf) {
        const int c0 = ch * CC;
        for (int i = tid; i < CC * (BT + 2); i += 256) {
            const int cc = i / (BT + 2), p = i - cc * (BT + 2);
            const int t = t0 - 1 + p;
            const int c = c0 + cc;
            float v = 0.f;
            if (t >= 0 && t < T_) {
                v = xin[(b * CIN + c) * T_ + t];
                if constexpr (!IS1) v = fmaxf(fmaf(v, gA[c], gB[c]), 0.f);
            }
            xs[buf][cc][p] = v;
        }
        // coalesced: consecutive i -> consecutive u64 in d_wNd
        for (int i = tid; i < CC * BO * 3; i += 256) {
            const int cc = i / (BO * 3), r = i - cc * (BO * 3);
            wsd[buf][cc][r] = wsrc[(size_t)(c0 + cc) * (COUT * 3) + o0 * 3 + r];
        }
    };

    u64 acc2[OT][4];
#pragma unroll
    for (int j = 0; j < OT; j++)
#pragma unroll
        for (int i = 0; i < 4; i++) acc2[j][i] = 0ull;

    stage(0, 0);
    __syncthreads();

    for (int ch = 0; ch < NCH; ch++) {
        const int buf = ch & 1;
        if (ch + 1 < NCH) stage(ch + 1, buf ^ 1);   // overlap with compute

#pragma unroll
        for (int cc = 0; cc < CC; cc++) {
            const float4* xp = reinterpret_cast<const float4*>(&xs[buf][cc][tx * 8]);
            const float4 a0 = xp[0], a1 = xp[1], a2 = xp[2];
            u64 pe[5], po[4];
            pe[0] = pk2(a0.x, a0.y); pe[1] = pk2(a0.z, a0.w);
            pe[2] = pk2(a1.x, a1.y); pe[3] = pk2(a1.z, a1.w);
            pe[4] = pk2(a2.x, a2.y);
            po[0] = pk2(a0.y, a0.z); po[1] = pk2(a0.w, a1.x);
            po[2] = pk2(a1.y, a1.z); po[3] = pk2(a1.w, a2.x);

            const u64* wrow = &wsd[buf][cc][0];
#pragma unroll
            for (int j = 0; j < OT; j++) {
                const int ol = ty * OT + j;
                const u64 w0 = wrow[ol * 3 + 0];
                const u64 w1v = wrow[ol * 3 + 1];
                const u64 w2 = wrow[ol * 3 + 2];
#pragma unroll
                for (int i = 0; i < 4; i++) {
                    ffma2(acc2[j][i], w0, pe[i]);
                    ffma2(acc2[j][i], w1v, po[i]);
                    ffma2(acc2[j][i], w2, pe[i + 1]);
                }
            }
        }
        __syncthreads();   // one barrier per chunk
    }

    // ------------------------- epilogue ------------------------------------
    float ov[OT][8];
#pragma unroll
    for (int j = 0; j < OT; j++)
#pragma unroll
        for (int i = 0; i < 4; i++)
            upk2(ov[j][2 * i], ov[j][2 * i + 1], acc2[j][i]);

    if constexpr (IS1) {
        const float4* sd4 = reinterpret_cast<const float4*>(
            d_sdot + (size_t)b * NCLS * 3 * C1);
        const int oq = (o0 >> 2) + ty;
#pragma unroll
        for (int i = 0; i < 8; i++) {
            const int tl = tx * 8 + i;
            const int t = t0 + tl;
            float4 s1 = sd4[(size_t)(sam[tl + 1] * 3 + 1) * 32 + oq];
            ov[0][i] += s1.x + sg[BO + ty * 4 + 0];
            ov[1][i] += s1.y + sg[BO + ty * 4 + 1];
            ov[2][i] += s1.z + sg[BO + ty * 4 + 2];
            ov[3][i] += s1.w + sg[BO + ty * 4 + 3];
            if (t > 0) {
                float4 s0 = sd4[(size_t)(sam[tl] * 3 + 0) * 32 + oq];
                ov[0][i] += s0.x + sg[ty * 4 + 0];
                ov[1][i] += s0.y + sg[ty * 4 + 1];
                ov[2][i] += s0.z + sg[ty * 4 + 2];
                ov[3][i] += s0.w + sg[ty * 4 + 3];
            }
            if (t < T_ - 1) {
                float4 s2 = sd4[(size_t)(sam[tl + 2] * 3 + 2) * 32 + oq];
                ov[0][i] += s2.x + sg[2 * BO + ty * 4 + 0];
                ov[1][i] += s2.y + sg[2 * BO + ty * 4 + 1];
                ov[2][i] += s2.z + sg[2 * BO + ty * 4 + 2];
                ov[3][i] += s2.w + sg[2 * BO + ty * 4 + 3];
            }
        }
    }

#pragma unroll
    for (int j = 0; j < OT; j++) {
        const int ol = ty * OT + j;
        const float bo = sb[ol];
        float4* yp = reinterpret_cast<float4*>(
            y + (size_t)(b * COUT + o0 + ol) * T_ + t0 + tx * 8);
        yp[0] = make_float4(ov[j][0] + bo, ov[j][1] + bo, ov[j][2] + bo, ov[j][3] + bo);
        yp[1] = make_float4(ov[j][4] + bo, ov[j][5] + bo, ov[j][6] + bo, ov[j][7] + bo);
    }
}

// ------------------------- GN stats ----------------------------------------
template <int STAGE>
__global__ void __launch_bounds__(256) k_gnstats() {
    constexpr int C   = (STAGE == 1) ? C1 : (STAGE == 2) ? C2 : C3;
    constexpr int CPG = C / 32;
    constexpr int N   = CPG * T_;
    const float* yv  = (STAGE == 1) ? d_y1 : (STAGE == 2) ? d_y2 : d_y3;
    float* meanp = (STAGE == 1) ? d_mean1 : (STAGE == 2) ? d_mean2 : d_mean3;
    float* rstdp = (STAGE == 1) ? d_rstd1 : (STAGE == 2) ? d_rstd2 : d_rstd3;

    const int bg = blockIdx.x;
    const float4* p = reinterpret_cast<const float4*>(
        yv + (size_t)(bg / 32) * C * T_ + (size_t)(bg % 32) * CPG * T_);
    float s = 0.f, s2 = 0.f;
    for (int i = threadIdx.x; i < N / 4; i += 256) {
        const float4 v = p[i];
        s += v.x + v.y + v.z + v.w;
        s2 = fmaf(v.x, v.x, fmaf(v.y, v.y, fmaf(v.z, v.z, fmaf(v.w, v.w, s2))));
    }
    __shared__ float ss[8], ss2[8];
#pragma unroll
    for (int o = 16; o; o >>= 1) {
        s  += __shfl_down_sync(0xffffffffu, s,  o);
        s2 += __shfl_down_sync(0xffffffffu, s2, o);
    }
    if ((threadIdx.x & 31) == 0) { ss[threadIdx.x >> 5] = s; ss2[threadIdx.x >> 5] = s2; }
    __syncthreads();
    if (threadIdx.x == 0) {
        float S = 0.f, S2 = 0.f;
#pragma unroll
        for (int i = 0; i < 8; i++) { S += ss[i]; S2 += ss2[i]; }
        const float m = S / N;
        const float var = S2 / N - m * m;
        meanp[bg] = m;
        rstdp[bg] = rsqrtf(var + 1e-5f);
    }
}

// ------------------------- conv4 (k=1) + output affine ---------------------
__global__ void __launch_bounds__(256)
k_out(const float* __restrict__ w4, const float* __restrict__ b4,
      const float* __restrict__ s3, const float* __restrict__ bb3,
      const float* __restrict__ omean, const float* __restrict__ ostd,
      float* __restrict__ out) {
    const int b = blockIdx.y;
    const int t = blockIdx.x * 256 + threadIdx.x;
    __shared__ float A[32], Bc[32], W[32];
    if (threadIdx.x < 32) {
        const int c = threadIdx.x;
        const float a = d_rstd3[b * 32 + c] * s3[c];
        A[c] = a;
        Bc[c] = bb3[c] - d_mean3[b * 32 + c] * a;
        W[c] = w4[c];
    }
    __syncthreads();
    float acc = b4[0];
#pragma unroll
    for (int c = 0; c < 32; c++) {
        float v = d_y3[(b * 32 + c) * T_ + t];
        v = fmaxf(fmaf(v, A[c], Bc[c]), 0.f);
        acc = fmaf(W[c], v, acc);
    }
    out[(size_t)t * NB + b] = fmaf(acc, ostd[0], omean[0]);
}

// ------------------------- launch ------------------------------------------
extern "C" void kernel_launch(void* const* d_in, const int* in_sizes, int n_in,
                              void* d_out, int out_size) {
    const float* input      = (const float*)d_in[0];
    const float* g_style    = (const float*)d_in[1];
    const float* char_style = (const float*)d_in[3];
    const float* c1w = (const float*)d_in[4];
    const float* c1b = (const float*)d_in[5];
    const float* g1s = (const float*)d_in[6];
    const float* g1b = (const float*)d_in[7];
    const float* c2w = (const float*)d_in[8];
    const float* c2b = (const float*)d_in[9];
    const float* g2s = (const float*)d_in[10];
    const float* g2b = (const float*)d_in[11];
    const float* c3w = (const float*)d_in[12];
    const float* c3b = (const float*)d_in[13];
    const float* g3s = (const float*)d_in[14];
    const float* g3b = (const float*)d_in[15];
    const float* c4w = (const float*)d_in[16];
    const float* c4b = (const float*)d_in[17];
    const float* om  = (const float*)d_in[18];
    const float* os  = (const float*)d_in[19];
    float* out = (float*)d_out;

    // weight transforms (tiny, once per launch)
    u64 *w1d, *w2d, *w3d;
    cudaGetSymbolAddress((void**)&w1d, d_w1d);
    cudaGetSymbolAddress((void**)&w2d, d_w2d);
    cudaGetSymbolAddress((void**)&w3d, d_w3d);
    k_wdup<<<(NCLS * C1 * 3 + 255) / 256, 256>>>(c1w, w1d, CIN1W, C1, NCLS * C1 * 3);
    k_wdup<<<(C1 * C2 * 3 + 255) / 256, 256>>>(c2w, w2d, C1, C2, C1 * C2 * 3);
    k_wdup<<<(C2 * C3 * 3 + 255) / 256, 256>>>(c3w, w3d, C2, C3, C2 * C3 * 3);

    k_prep<<<dim3(T_ / 128, NB), 128>>>(input);
    k_gdot<<<NB, 384>>>(g_style, c1w);
    k_sdot<<<dim3(NCLS, NB), 384>>>(char_style, c1w);

    k_conv<1><<<dim3(T_ / 128, C1 / 64, NB), 256>>>(c1b, nullptr, nullptr);
    k_gnstats<1><<<NB * 32, 256>>>();

    k_conv<2><<<dim3(T_ / 128, 1, NB), 256>>>(c2b, g1s, g1b);
    k_gnstats<2><<<NB * 32, 256>>>();

    k_conv<3><<<dim3(T_ / 128, 1, NB), 256>>>(c3b, g2s, g2b);
    k_gnstats<3><<<NB * 32, 256>>>();

    k_out<<<dim3(T_ / 256, NB), 256>>>(c4w, c4b, g3s, g3b, om, os, out);
}

// round 11
// speedup vs baseline: 1.2662x; 1.0868x over previous
#include <cuda_runtime.h>
#include <cuda_bf16.h>
#include <cstdint>

// ---------------------------------------------------------------------------
// CharCountCNN — round 11: convs as warp-level bf16 mma.sync GEMMs (sm_80+
// HMMA path; tcgen05 unavailable at compute_100). Hi/lo split (3 products)
// for fp32-grade accuracy. Argmax gather + gdot + bias folded into the GEMM
// via one-hot / const input channels. GN stats fused via atomics.
// ---------------------------------------------------------------------------

using u32 = unsigned int;
using u64 = unsigned long long;

constexpr int T_ = 1024, NB = 128, NCLS = 80, NSTY = 256, NCS = 64;
constexpr int C1 = 128, C2 = 64, C3 = 32, CIN1W = 400;

// ------------------------- global scratch ----------------------------------
__device__ float d_xin [NB * NCLS * T_];
__device__ int   d_amax[NB * T_];
__device__ float d_gdot[NB * 3 * C1];            // [b][k][o]
__device__ float d_sdot[NB * NCLS * 3 * C1];     // [b][ch][k][o]
__device__ float d_y1[NB * C1 * T_], d_y2[NB * C2 * T_], d_y3[NB * C3 * T_];
__device__ float d_osum[3 * NB * 128], d_osq[3 * NB * 128];
__device__ float d_meanA[3 * NB * 32], d_rstdA[3 * NB * 32];
// packed (2x bf16) weight images, zero-padded: [k][o][col-pair]
__device__ u32 d_wh1u[3 * 128 * 88], d_wl1u[3 * 128 * 88];
__device__ u32 d_wh2u[3 * 64 * 72],  d_wl2u[3 * 64 * 72];
__device__ u32 d_wh3u[3 * 32 * 40],  d_wl3u[3 * 32 * 40];
// per-b stage-1 extra cols (sdot 80 + gdot/bias 1 + pad): [b][k][o][42 pairs]
__device__ u32 d_s1hu[NB * 3 * 128 * 42], d_s1lu[NB * 3 * 128 * 42];

// ------------------------- helpers -----------------------------------------
__device__ __forceinline__ u32 smem_u32(const void* p) {
    u32 a;
    asm("{ .reg .u64 t; cvta.to.shared.u64 t, %1; cvt.u32.u64 %0, t; }"
        : "=r"(a) : "l"(p));
    return a;
}
__device__ __forceinline__ void sts32(u32 a, u32 v) {
    asm volatile("st.shared.u32 [%0], %1;" :: "r"(a), "r"(v) : "memory");
}
__device__ __forceinline__ void ldsm_x4(u32* r, u32 a) {
    asm volatile("ldmatrix.sync.aligned.m8n8.x4.shared.b16 {%0,%1,%2,%3}, [%4];"
                 : "=r"(r[0]), "=r"(r[1]), "=r"(r[2]), "=r"(r[3]) : "r"(a));
}
__device__ __forceinline__ void ldsm_x2(u32* r, u32 a) {
    asm volatile("ldmatrix.sync.aligned.m8n8.x2.shared.b16 {%0,%1}, [%2];"
                 : "=r"(r[0]), "=r"(r[1]) : "r"(a));
}
__device__ __forceinline__ void mma_bf16(float* d, const u32* A, const u32* B) {
    asm volatile(
        "mma.sync.aligned.m16n8k16.row.col.f32.bf16.bf16.f32 "
        "{%0,%1,%2,%3}, {%4,%5,%6,%7}, {%8,%9}, {%0,%1,%2,%3};"
        : "+f"(d[0]), "+f"(d[1]), "+f"(d[2]), "+f"(d[3])
        : "r"(A[0]), "r"(A[1]), "r"(A[2]), "r"(A[3]), "r"(B[0]), "r"(B[1]));
}
__device__ __forceinline__ void split2(float v0, float v1, u32& hp, u32& lp) {
    __nv_bfloat16 h0 = __float2bfloat16(v0);
    __nv_bfloat16 h1 = __float2bfloat16(v1);
    __nv_bfloat16 l0 = __float2bfloat16(v0 - __bfloat162float(h0));
    __nv_bfloat16 l1 = __float2bfloat16(v1 - __bfloat162float(h1));
    hp = ((u32)__bfloat16_as_ushort(h1) << 16) | __bfloat16_as_ushort(h0);
    lp = ((u32)__bfloat16_as_ushort(l1) << 16) | __bfloat16_as_ushort(l0);
}

// ------------------------- K0: argmax + transpose --------------------------
__global__ void __launch_bounds__(128) k_prep(const float* __restrict__ inp) {
    __shared__ float s[128][NCLS + 1];
    const int b = blockIdx.y, t0 = blockIdx.x * 128, tid = threadIdx.x;
    const float4* row = reinterpret_cast<const float4*>(
        inp + ((size_t)(t0 + tid) * NB + b) * NCLS);
    float best = -3.4e38f;
    int bi = 0;
#pragma unroll
    for (int c4 = 0; c4 < NCLS / 4; c4++) {
        float4 v = row[c4];
        int c = c4 * 4;
        s[tid][c + 0] = v.x; s[tid][c + 1] = v.y;
        s[tid][c + 2] = v.z; s[tid][c + 3] = v.w;
        if (v.x > best) { best = v.x; bi = c + 0; }
        if (v.y > best) { best = v.y; bi = c + 1; }
        if (v.z > best) { best = v.z; bi = c + 2; }
        if (v.w > best) { best = v.w; bi = c + 3; }
    }
    d_amax[b * T_ + t0 + tid] = bi;
    __syncthreads();
#pragma unroll 4
    for (int c = 0; c < NCLS; c++)
        d_xin[(b * NCLS + c) * T_ + t0 + tid] = s[tid][c];
}

// ------------------------- K1/K2: gdot, sdot -------------------------------
__global__ void __launch_bounds__(384) k_gdot(const float* __restrict__ g_style,
                                              const float* __restrict__ w1) {
    __shared__ float gs[NSTY];
    const int b = blockIdx.x, tid = threadIdx.x;
    for (int c = tid; c < NSTY; c += 384) gs[c] = g_style[b * NSTY + c];
    __syncthreads();
    const int o = tid / 3, k = tid % 3;
    const float* wp = w1 + o * (CIN1W * 3) + NCLS * 3 + k;
    float acc = 0.f;
#pragma unroll 8
    for (int c = 0; c < NSTY; c++) acc = fmaf(gs[c], wp[c * 3], acc);
    d_gdot[b * 3 * C1 + k * C1 + o] = acc;
}
__global__ void __launch_bounds__(384) k_sdot(const float* __restrict__ char_style,
                                              const float* __restrict__ w1) {
    __shared__ float cs[NCS];
    const int ch = blockIdx.x, b = blockIdx.y, tid = threadIdx.x;
    for (int c = tid; c < NCS; c += 384)
        cs[c] = char_style[((size_t)b * NCLS + ch) * NCS + c];
    __syncthreads();
    const int o = tid / 3, k = tid % 3;
    const float* wp = w1 + o * (CIN1W * 3) + (NCLS + NSTY) * 3 + k;
    float acc = 0.f;
#pragma unroll 8
    for (int c = 0; c < NCS; c++) acc = fmaf(cs[c], wp[c * 3], acc);
    d_sdot[((size_t)b * NCLS + ch) * 3 * C1 + k * C1 + o] = acc;
}

// ------------------------- weight prep (static part) -----------------------
template <int S>
__global__ void __launch_bounds__(256) k_wprep(const float* __restrict__ w,
                                               const float* __restrict__ bias) {
    constexpr int CIN  = (S == 1) ? NCLS : (S == 2) ? C1 : C2;
    constexpr int COUT = (S == 1) ? C1   : (S == 2) ? C2 : C3;
    constexpr int CINW = (S == 1) ? CIN1W : CIN;
    constexpr int CP2  = (S == 1) ? 88 : (S == 2) ? 72 : 40;
    u32* dh = (S == 1) ? d_wh1u : (S == 2) ? d_wh2u : d_wh3u;
    u32* dl = (S == 1) ? d_wl1u : (S == 2) ? d_wl2u : d_wl3u;
    const int i = blockIdx.x * 256 + threadIdx.x;
    if (i >= 3 * COUT * CP2) return;
    const int jp = i % CP2, o = (i / CP2) % COUT, k = i / (CP2 * COUT);
    auto val = [&](int c) -> float {
        if (c < CIN) return w[(o * CINW + c) * 3 + k];
        if (S > 1 && c == CIN) return (k == 1) ? bias[o] : 0.f;
        return 0.f;
    };
    u32 hp, lp;
    split2(val(2 * jp), val(2 * jp + 1), hp, lp);
    dh[i] = hp; dl[i] = lp;
}

// per-b stage-1 extras: cols 80..163 (sdot 80..159, gdot+bias 160, pad)
__global__ void __launch_bounds__(256) k_sprep(const float* __restrict__ bias) {
    const int i = blockIdx.x * 256 + threadIdx.x;
    if (i >= NB * 3 * 128 * 42) return;
    const int jp = i % 42, o = (i / 42) % 128;
    const int k = (i / (42 * 128)) % 3, b = i / (42 * 128 * 3);
    auto val = [&](int c) -> float {
        if (c < 160) return d_sdot[(((b * 80) + (c - 80)) * 3 + k) * 128 + o];
        if (c == 160) return d_gdot[(b * 3 + k) * 128 + o] + ((k == 1) ? bias[o] : 0.f);
        return 0.f;
    };
    const int c0 = 80 + 2 * jp;
    u32 hp, lp;
    split2(val(c0), val(c0 + 1), hp, lp);
    d_s1hu[i] = hp; d_s1lu[i] = lp;
}

__global__ void __launch_bounds__(256) k_zero() {
    const int i = blockIdx.x * 256 + threadIdx.x;
    if (i < 3 * NB * 128) { d_osum[i] = 0.f; d_osq[i] = 0.f; }
}

// ------------------------- conv via warp MMA -------------------------------
// grid (8, NB), 256 threads. Dynamic smem: [Xh][Xl][Wh][Wl][gn coefs]
template <int S>
__global__ void __launch_bounds__(256)
k_cmma(const float* __restrict__ gns, const float* __restrict__ gnb) {
    constexpr int CIN  = (S == 1) ? NCLS : (S == 2) ? C1 : C2;
    constexpr int COUT = (S == 1) ? C1   : (S == 2) ? C2 : C3;
    constexpr int CPAD = (S == 1) ? 176 : (S == 2) ? 144 : 80;
    constexpr int CP2  = CPAD / 2;
    constexpr int SROW = CPAD * 2 + 16;
    constexpr int KC   = CPAD / 16;
    constexpr int WT   = (S == 1) ? 4 : 8;     // warps along t
    constexpr int MT   = (S == 1) ? 2 : 1;     // m16 tiles per warp
    constexpr int NT   = (S == 1) ? 8 : (S == 2) ? 8 : 4;

    const float* xprev = (S == 1) ? d_xin : (S == 2) ? d_y1 : d_y2;
    float* y = (S == 1) ? d_y1 : (S == 2) ? d_y2 : d_y3;
    const u32* whsrc = (S == 1) ? d_wh1u : (S == 2) ? d_wh2u : d_wh3u;
    const u32* wlsrc = (S == 1) ? d_wl1u : (S == 2) ? d_wl2u : d_wl3u;

    extern __shared__ char dynsm[];
    const u32 sb0 = smem_u32(dynsm);
    const u32 sb = (sb0 + 127) & ~127u;
    char* bp = dynsm + (sb - sb0);
    const u32 xh = sb;
    const u32 xl = xh + 130 * SROW;
    const u32 wh = xl + 130 * SROW;
    const u32 wl = wh + COUT * SROW;
    float* gA = (float*)(bp + 2 * 130 * SROW + 2 * COUT * SROW);
    float* gB = gA + CIN;

    const int b = blockIdx.y, t0 = blockIdx.x * 128;
    const int tid = threadIdx.x, wid = tid >> 5, lid = tid & 31;

    if constexpr (S > 1) {
        const float* pm = d_meanA + (S - 2) * NB * 32;
        const float* pr = d_rstdA + (S - 2) * NB * 32;
        for (int c = tid; c < CIN; c += 256) {
            const int g = c / (CIN / 32);
            const float a = pr[b * 32 + g] * gns[c];
            gA[c] = a;
            gB[c] = gnb[c] - pm[b * 32 + g] * a;
        }
        __syncthreads();
    }

    // ---- stage X (rows p=0..129 -> t = t0-1+p), hi/lo split ----
    for (int i = tid; i < CP2 * 130; i += 256) {
        const int jp = i / 130, p = i - jp * 130;
        const int t = t0 - 1 + p;
        const int c0 = jp * 2;
        float v0 = 0.f, v1 = 0.f;
        if (t >= 0 && t < T_) {
            if constexpr (S == 1) {
                if (c0 < 80) {
                    v0 = d_xin[(b * 80 + c0) * T_ + t];
                    v1 = d_xin[(b * 80 + c0 + 1) * T_ + t];
                } else if (c0 < 160) {
                    const int am = d_amax[b * T_ + t];
                    v0 = (am == c0 - 80) ? 1.f : 0.f;
                    v1 = (am == c0 - 79) ? 1.f : 0.f;
                } else if (c0 == 160) {
                    v0 = 1.f;
                }
            } else {
                if (c0 < CIN) {
                    const float a0 = xprev[((size_t)b * CIN + c0) * T_ + t];
                    const float a1 = xprev[((size_t)b * CIN + c0 + 1) * T_ + t];
                    v0 = fmaxf(fmaf(a0, gA[c0], gB[c0]), 0.f);
                    v1 = fmaxf(fmaf(a1, gA[c0 + 1], gB[c0 + 1]), 0.f);
                } else if (c0 == CIN) {
                    v0 = 1.f;
                }
            }
        }
        u32 hp, lp;
        split2(v0, v1, hp, lp);
        sts32(xh + p * SROW + jp * 4, hp);
        sts32(xl + p * SROW + jp * 4, lp);
    }

    const int wt = (S == 1) ? (wid & 3) : wid;
    const int wo = (S == 1) ? (wid >> 2) : 0;
    const int o0w = (S == 1) ? wo * 64 : 0;

    float acc[MT][NT][4];
#pragma unroll
    for (int mt = 0; mt < MT; mt++)
#pragma unroll
        for (int nt = 0; nt < NT; nt++)
#pragma unroll
            for (int d = 0; d < 4; d++) acc[mt][nt][d] = 0.f;

    const int arow = lid & 15, acol = (lid >> 4) * 16;
    const int brow = lid & 7,  bcol = ((lid >> 3) & 1) * 16;

    for (int k = 0; k < 3; k++) {
        // stage W_k (static part; S1 skips per-b region)
        for (int i = tid; i < COUT * CP2; i += 256) {
            const int o = i / CP2, jp = i - o * CP2;
            if (S == 1 && jp >= 40 && jp < 82) continue;
            const int src = (k * COUT + o) * CP2 + jp;
            sts32(wh + o * SROW + jp * 4, whsrc[src]);
            sts32(wl + o * SROW + jp * 4, wlsrc[src]);
        }
        if constexpr (S == 1) {
            for (int i = tid; i < 128 * 42; i += 256) {
                const int o = i / 42, jp = i - o * 42;
                const int src = ((b * 3 + k) * 128 + o) * 42 + jp;
                sts32(wh + o * SROW + 160 + jp * 4, d_s1hu[src]);
                sts32(wl + o * SROW + 160 + jp * 4, d_s1lu[src]);
            }
        }
        __syncthreads();

        for (int kc = 0; kc < KC; kc++) {
            u32 Ah[MT][4], Al[MT][4];
#pragma unroll
            for (int mt = 0; mt < MT; mt++) {
                const int p0 = wt * (128 / WT) + mt * 16 + k;
                const u32 ab = xh + (p0 + arow) * SROW + kc * 32 + acol;
                ldsm_x4(Ah[mt], ab);
                ldsm_x4(Al[mt], ab + 130 * SROW);
            }
#pragma unroll
            for (int nt = 0; nt < NT; nt++) {
                const u32 bb = wh + (o0w + nt * 8 + brow) * SROW + kc * 32 + bcol;
                u32 Bh[2], Bl[2];
                ldsm_x2(Bh, bb);
                ldsm_x2(Bl, bb + COUT * SROW);
#pragma unroll
                for (int mt = 0; mt < MT; mt++) {
                    mma_bf16(acc[mt][nt], Ah[mt], Bh);
                    mma_bf16(acc[mt][nt], Ah[mt], Bl);
                    mma_bf16(acc[mt][nt], Al[mt], Bh);
                }
            }
        }
        __syncthreads();
    }

    // ---- epilogue: store + GN partial sums ----
    const int tb = t0 + wt * (128 / WT);
    float* osum = d_osum + (S - 1) * NB * 128 + b * COUT;
    float* osq  = d_osq  + (S - 1) * NB * 128 + b * COUT;
#pragma unroll
    for (int mt = 0; mt < MT; mt++) {
#pragma unroll
        for (int nt = 0; nt < NT; nt++) {
            const int tt = tb + mt * 16 + (lid >> 2);
            const int oo = o0w + nt * 8 + (lid & 3) * 2;
            float* yp = &y[((size_t)b * COUT + oo) * T_ + tt];
            yp[0]      = acc[mt][nt][0];
            yp[8]      = acc[mt][nt][2];
            yp[T_]     = acc[mt][nt][1];
            yp[T_ + 8] = acc[mt][nt][3];
        }
    }
#pragma unroll
    for (int nt = 0; nt < NT; nt++) {
#pragma unroll
        for (int jj = 0; jj < 2; jj++) {
            float s = 0.f, q = 0.f;
#pragma unroll
            for (int mt = 0; mt < MT; mt++) {
                const float a = acc[mt][nt][jj], c2 = acc[mt][nt][2 + jj];
                s += a + c2;
                q = fmaf(a, a, fmaf(c2, c2, q));
            }
            s += __shfl_xor_sync(~0u, s, 4);  q += __shfl_xor_sync(~0u, q, 4);
            s += __shfl_xor_sync(~0u, s, 8);  q += __shfl_xor_sync(~0u, q, 8);
            s += __shfl_xor_sync(~0u, s, 16); q += __shfl_xor_sync(~0u, q, 16);
            if ((lid >> 2) == 0) {
                const int oo = o0w + nt * 8 + (lid & 3) * 2 + jj;
                atomicAdd(&osum[oo], s);
                atomicAdd(&osq[oo], q);
            }
        }
    }
}

// ------------------------- GN finalize -------------------------------------
template <int S>
__global__ void __launch_bounds__(256) k_gnfin() {
    constexpr int COUT = (S == 1) ? C1 : (S == 2) ? C2 : C3;
    constexpr int CPG = COUT / 32;
    const int i = blockIdx.x * 256 + threadIdx.x;
    if (i >= NB * 32) return;
    const int b = i / 32, g = i % 32;
    const float* os = d_osum + (S - 1) * NB * 128 + b * COUT + g * CPG;
    const float* oq = d_osq  + (S - 1) * NB * 128 + b * COUT + g * CPG;
    float s = 0.f, q = 0.f;
#pragma unroll
    for (int j = 0; j < CPG; j++) { s += os[j]; q += oq[j]; }
    const float N = (float)(CPG * T_);
    const float m = s / N;
    d_meanA[(S - 1) * NB * 32 + i] = m;
    d_rstdA[(S - 1) * NB * 32 + i] = rsqrtf(q / N - m * m + 1e-5f);
}

// ------------------------- conv4 (k=1) + output affine ---------------------
__global__ void __launch_bounds__(256)
k_out(const float* __restrict__ w4, const float* __restrict__ b4,
      const float* __restrict__ s3, const float* __restrict__ bb3,
      const float* __restrict__ omean, const float* __restrict__ ostd,
      float* __restrict__ out) {
    const int b = blockIdx.y;
    const int t = blockIdx.x * 256 + threadIdx.x;
    __shared__ float A[32], Bc[32], W[32];
    if (threadIdx.x < 32) {
        const int c = threadIdx.x;
        const float a = d_rstdA[2 * NB * 32 + b * 32 + c] * s3[c];
        A[c] = a;
        Bc[c] = bb3[c] - d_meanA[2 * NB * 32 + b * 32 + c] * a;
        W[c] = w4[c];
    }
    __syncthreads();
    float acc = b4[0];
#pragma unroll
    for (int c = 0; c < 32; c++) {
        float v = d_y3[(b * 32 + c) * T_ + t];
        v = fmaxf(fmaf(v, A[c], Bc[c]), 0.f);
        acc = fmaf(W[c], v, acc);
    }
    out[(size_t)t * NB + b] = fmaf(acc, ostd[0], omean[0]);
}

// ------------------------- launch ------------------------------------------
constexpr int SROW1 = 176 * 2 + 16, SROW2 = 144 * 2 + 16, SROW3 = 80 * 2 + 16;
constexpr int SM1 = 2 * 130 * SROW1 + 2 * 128 * SROW1 + 256;
constexpr int SM2 = 2 * 130 * SROW2 + 2 * 64 * SROW2 + 2 * 128 * 4 + 256;
constexpr int SM3 = 2 * 130 * SROW3 + 2 * 32 * SROW3 + 2 * 64 * 4 + 256;

extern "C" void kernel_launch(void* const* d_in, const int* in_sizes, int n_in,
                              void* d_out, int out_size) {
    const float* input      = (const float*)d_in[0];
    const float* g_style    = (const float*)d_in[1];
    const float* char_style = (const float*)d_in[3];
    const float* c1w = (const float*)d_in[4];
    const float* c1b = (const float*)d_in[5];
    const float* g1s = (const float*)d_in[6];
    const float* g1b = (const float*)d_in[7];
    const float* c2w = (const float*)d_in[8];
    const float* c2b = (const float*)d_in[9];
    const float* g2s = (const float*)d_in[10];
    const float* g2b = (const float*)d_in[11];
    const float* c3w = (const float*)d_in[12];
    const float* c3b = (const float*)d_in[13];
    const float* g3s = (const float*)d_in[14];
    const float* g3b = (const float*)d_in[15];
    const float* c4w = (const float*)d_in[16];
    const float* c4b = (const float*)d_in[17];
    const float* om  = (const float*)d_in[18];
    const float* os  = (const float*)d_in[19];
    float* out = (float*)d_out;

    cudaFuncSetAttribute(k_cmma<1>, cudaFuncAttributeMaxDynamicSharedMemorySize, SM1);
    cudaFuncSetAttribute(k_cmma<2>, cudaFuncAttributeMaxDynamicSharedMemorySize, SM2);
    cudaFuncSetAttribute(k_cmma<3>, cudaFuncAttributeMaxDynamicSharedMemorySize, SM3);

    k_wprep<1><<<(3 * 128 * 88 + 255) / 256, 256>>>(c1w, c1b);
    k_wprep<2><<<(3 * 64 * 72 + 255) / 256, 256>>>(c2w, c2b);
    k_wprep<3><<<(3 * 32 * 40 + 255) / 256, 256>>>(c3w, c3b);
    k_prep<<<dim3(T_ / 128, NB), 128>>>(input);
    k_gdot<<<NB, 384>>>(g_style, c1w);
    k_sdot<<<dim3(NCLS, NB), 384>>>(char_style, c1w);
    k_sprep<<<(NB * 3 * 128 * 42 + 255) / 256, 256>>>(c1b);
    k_zero<<<(3 * NB * 128 + 255) / 256, 256>>>();

    k_cmma<1><<<dim3(8, NB), 256, SM1>>>(nullptr, nullptr);
    k_gnfin<1><<<(NB * 32 + 255) / 256, 256>>>();

    k_cmma<2><<<dim3(8, NB), 256, SM2>>>(g1s, g1b);
    k_gnfin<2><<<(NB * 32 + 255) / 256, 256>>>();

    k_cmma<3><<<dim3(8, NB), 256, SM3>>>(g2s, g2b);
    k_gnfin<3><<<(NB * 32 + 255) / 256, 256>>>();

    k_out<<<dim3(T_ / 256, NB), 256>>>(c4w, c4b, g3s, g3b, om, os, out);
}

// round 13
// speedup vs baseline: 1.8816x; 1.4860x over previous
#include <cuda_runtime.h>
#include <cuda_bf16.h>
#include <cstdint>

// ---------------------------------------------------------------------------
// CharCountCNN — round 13 (= round 12 resubmit after infra failure):
// warp-MMA bf16 convs, restructured:
//   * char_style gather folded into smem STAGING (dense 64 ch), no one-hot
//   * smaller tiles -> 2/3/4 CTAs/SM (staging/MMA overlap across CTAs)
//   * no d_xin transpose; stage-1 reads input[t][b][c] directly
//   * hi/lo bf16 split (3 products) for fp32-grade accuracy
// ---------------------------------------------------------------------------

using u32 = unsigned int;

constexpr int T_ = 1024, NB = 128, NCLS = 80, NSTY = 256;
constexpr int C1 = 128, C2 = 64, C3 = 32, CIN1W = 400;

// ------------------------- global scratch ----------------------------------
__device__ int   d_amax[NB * T_];                 // [t*NB + b]
__device__ float d_g1w[NB * 3 * C1];              // gdot + bias(k=1): [b][k][o]
__device__ float d_y1[NB * C1 * T_], d_y2[NB * C2 * T_], d_y3[NB * C3 * T_];
__device__ float d_osum[3 * NB * 128], d_osq[3 * NB * 128];
__device__ float d_meanA[3 * NB * 32], d_rstdA[3 * NB * 32];
// packed bf16-pair weight images [k][COUT][CP2]
__device__ u32 d_wh1u[3 * 128 * 80], d_wl1u[3 * 128 * 80];   // cols 0..159
__device__ u32 d_wh2u[3 * 64 * 64],  d_wl2u[3 * 64 * 64];    // cols 0..127
__device__ u32 d_wh3u[3 * 32 * 32],  d_wl3u[3 * 32 * 32];    // cols 0..63

// ------------------------- helpers -----------------------------------------
__device__ __forceinline__ u32 smem_u32(const void* p) {
    u32 a;
    asm("{ .reg .u64 t; cvta.to.shared.u64 t, %1; cvt.u32.u64 %0, t; }"
        : "=r"(a) : "l"(p));
    return a;
}
__device__ __forceinline__ void sts32(u32 a, u32 v) {
    asm volatile("st.shared.u32 [%0], %1;" :: "r"(a), "r"(v) : "memory");
}
__device__ __forceinline__ void ldsm_x4(u32* r, u32 a) {
    asm volatile("ldmatrix.sync.aligned.m8n8.x4.shared.b16 {%0,%1,%2,%3}, [%4];"
                 : "=r"(r[0]), "=r"(r[1]), "=r"(r[2]), "=r"(r[3]) : "r"(a));
}
__device__ __forceinline__ void ldsm_x2(u32* r, u32 a) {
    asm volatile("ldmatrix.sync.aligned.m8n8.x2.shared.b16 {%0,%1}, [%2];"
                 : "=r"(r[0]), "=r"(r[1]) : "r"(a));
}
__device__ __forceinline__ void mma_bf16(float* d, const u32* A, const u32* B) {
    asm volatile(
        "mma.sync.aligned.m16n8k16.row.col.f32.bf16.bf16.f32 "
        "{%0,%1,%2,%3}, {%4,%5,%6,%7}, {%8,%9}, {%0,%1,%2,%3};"
        : "+f"(d[0]), "+f"(d[1]), "+f"(d[2]), "+f"(d[3])
        : "r"(A[0]), "r"(A[1]), "r"(A[2]), "r"(A[3]), "r"(B[0]), "r"(B[1]));
}
__device__ __forceinline__ void split2(float v0, float v1, u32& hp, u32& lp) {
    __nv_bfloat16 h0 = __float2bfloat16(v0);
    __nv_bfloat16 h1 = __float2bfloat16(v1);
    __nv_bfloat16 l0 = __float2bfloat16(v0 - __bfloat162float(h0));
    __nv_bfloat16 l1 = __float2bfloat16(v1 - __bfloat162float(h1));
    hp = ((u32)__bfloat16_as_ushort(h1) << 16) | __bfloat16_as_ushort(h0);
    lp = ((u32)__bfloat16_as_ushort(l1) << 16) | __bfloat16_as_ushort(l0);
}

// ------------------------- weight prep -------------------------------------
template <int S>
__global__ void __launch_bounds__(256) k_wprep(const float* __restrict__ w) {
    constexpr int COUT = (S == 1) ? C1 : (S == 2) ? C2 : C3;
    constexpr int CINW = (S == 1) ? CIN1W : (S == 2) ? C1 : C2;
    constexpr int CP2  = (S == 1) ? 80 : (S == 2) ? 64 : 32;
    u32* dh = (S == 1) ? d_wh1u : (S == 2) ? d_wh2u : d_wh3u;
    u32* dl = (S == 1) ? d_wl1u : (S == 2) ? d_wl2u : d_wl3u;
    const int i = blockIdx.x * 256 + threadIdx.x;
    if (i >= 3 * COUT * CP2) return;
    const int jp = i % CP2, o = (i / CP2) % COUT, k = i / (CP2 * COUT);
    auto val = [&](int c) -> float {
        if constexpr (S == 1) {
            if (c < 80)  return w[(o * CIN1W + c) * 3 + k];
            if (c < 144) return w[(o * CIN1W + 336 + (c - 80)) * 3 + k];
            return 0.f;     // cols 144..159 (gdot col staged per-b)
        } else {
            if (c < CINW) return w[(o * CINW + c) * 3 + k];
            return 0.f;
        }
    };
    u32 hp, lp;
    split2(val(2 * jp), val(2 * jp + 1), hp, lp);
    dh[i] = hp; dl[i] = lp;
}

// ------------------------- argmax (+ zero GN accumulators) -----------------
__global__ void __launch_bounds__(256) k_amax(const float* __restrict__ inp) {
    const int r = blockIdx.x * 256 + threadIdx.x;   // r = t*NB + b
    if (r < 3 * NB * 128) { d_osum[r] = 0.f; d_osq[r] = 0.f; }
    const float4* row = reinterpret_cast<const float4*>(inp + (size_t)r * NCLS);
    float best = -3.4e38f;
    int bi = 0;
#pragma unroll
    for (int c4 = 0; c4 < NCLS / 4; c4++) {
        float4 v = row[c4];
        int c = c4 * 4;
        if (v.x > best) { best = v.x; bi = c + 0; }
        if (v.y > best) { best = v.y; bi = c + 1; }
        if (v.z > best) { best = v.z; bi = c + 2; }
        if (v.w > best) { best = v.w; bi = c + 3; }
    }
    d_amax[r] = bi;
}

// ------------------------- gdot (+bias at k=1) -----------------------------
__global__ void __launch_bounds__(384) k_gdot(const float* __restrict__ g_style,
                                              const float* __restrict__ w1,
                                              const float* __restrict__ b1) {
    __shared__ float gs[NSTY];
    const int b = blockIdx.x, tid = threadIdx.x;
    for (int c = tid; c < NSTY; c += 384) gs[c] = g_style[b * NSTY + c];
    __syncthreads();
    const int o = tid / 3, k = tid % 3;
    const float* wp = w1 + o * (CIN1W * 3) + NCLS * 3 + k;
    float acc = (k == 1) ? b1[o] : 0.f;
#pragma unroll 8
    for (int c = 0; c < NSTY; c++) acc = fmaf(gs[c], wp[c * 3], acc);
    d_g1w[b * 384 + k * 128 + o] = acc;
}

// ------------------------- conv via warp MMA -------------------------------
// 256 threads. grid (T_/TT, COUT/OT, NB).
template <int S>
__global__ void __launch_bounds__(256)
k_cmma(const float* __restrict__ p0a, const float* __restrict__ p1a,
       const float* __restrict__ p2a) {
    constexpr int CIN  = (S == 1) ? 80 : (S == 2) ? C1 : C2;
    constexpr int COUT = (S == 1) ? C1 : (S == 2) ? C2 : C3;
    constexpr int CPAD = (S == 1) ? 160 : (S == 2) ? 128 : 64;
    constexpr int CP2  = CPAD / 2;
    constexpr int SROW = CPAD * 2 + 16;
    constexpr int KC   = CPAD / 16;
    constexpr int TT   = (S == 3) ? 128 : 64;
    constexpr int OT   = (S == 3) ? 32 : 64;
    constexpr int WT   = (S == 3) ? 8 : 4;      // warps along t
    constexpr int XR   = TT + 2;

    const float* xprev = (S == 2) ? d_y1 : d_y2;   // S==3 uses d_y2
    float* y = (S == 1) ? d_y1 : (S == 2) ? d_y2 : d_y3;
    const u32* whsrc = (S == 1) ? d_wh1u : (S == 2) ? d_wh2u : d_wh3u;
    const u32* wlsrc = (S == 1) ? d_wl1u : (S == 2) ? d_wl2u : d_wl3u;

    extern __shared__ char dynsm[];
    const u32 sraw = smem_u32(dynsm);
    const u32 sbA = (sraw + 127) & ~127u;
    char* bp = dynsm + (sbA - sraw);
    const u32 xh = sbA, xl = xh + XR * SROW;
    const u32 wh = xl + XR * SROW, wl = wh + OT * SROW;
    char* auxp = bp + 2 * XR * SROW + 2 * OT * SROW;
    int*   sam = (int*)auxp;              // S1
    float* gA  = (float*)auxp;            // S>1
    float* gB  = gA + CIN;
    float* sb  = gB + CIN;

    const int b = blockIdx.z, t0 = blockIdx.x * TT, o0c = blockIdx.y * OT;
    const int tid = threadIdx.x, wid = tid >> 5, lid = tid & 31;
    const int wt = wid % WT, wo = wid / WT;

    // ---- aux staging ----
    if constexpr (S == 1) {
        for (int p = tid; p < XR; p += 256) {
            const int t = t0 - 1 + p;
            sam[p] = (t >= 0 && t < T_) ? d_amax[t * NB + b] : 0;
        }
    } else {
        const float* pm = d_meanA + (S - 2) * NB * 32;
        const float* pr = d_rstdA + (S - 2) * NB * 32;
        for (int c = tid; c < CIN; c += 256) {
            const int g = c / (CIN / 32);
            const float a = pr[b * 32 + g] * p0a[c];      // gns
            gA[c] = a;
            gB[c] = p1a[c] - pm[b * 32 + g] * a;          // gnb
        }
        for (int i = tid; i < OT; i += 256) sb[i] = p2a[o0c + i];   // bias
    }
    __syncthreads();

    // ---- X staging (hi/lo split) ----
    if constexpr (S == 1) {
        for (int i = tid; i < XR * CP2; i += 256) {
            const int p = i / CP2, jp = i - p * CP2;
            const int t = t0 - 1 + p;
            const int c0 = 2 * jp;
            float v0 = 0.f, v1 = 0.f;
            if (t >= 0 && t < T_) {
                if (c0 < 80) {
                    const float* ip = p0a + ((size_t)t * NB + b) * NCLS + c0;
                    v0 = ip[0]; v1 = ip[1];
                } else if (c0 < 144) {
                    const float* cp =
                        p1a + ((size_t)b * NCLS + sam[p]) * 64 + (c0 - 80);
                    v0 = cp[0]; v1 = cp[1];
                } else if (c0 == 144) {
                    v0 = 1.f;
                }
            }
            u32 hp, lp;
            split2(v0, v1, hp, lp);
            sts32(xh + p * SROW + jp * 4, hp);
            sts32(xl + p * SROW + jp * 4, lp);
        }
    } else {
        for (int i = tid; i < CP2 * XR; i += 256) {
            const int jp = i / XR, p = i - jp * XR;
            const int t = t0 - 1 + p;
            const int c0 = 2 * jp;
            float v0 = 0.f, v1 = 0.f;
            if (t >= 0 && t < T_) {
                const float a0 = xprev[((size_t)b * CIN + c0) * T_ + t];
                const float a1 = xprev[((size_t)b * CIN + c0 + 1) * T_ + t];
                v0 = fmaxf(fmaf(a0, gA[c0], gB[c0]), 0.f);
                v1 = fmaxf(fmaf(a1, gA[c0 + 1], gB[c0 + 1]), 0.f);
            }
            u32 hp, lp;
            split2(v0, v1, hp, lp);
            sts32(xh + p * SROW + jp * 4, hp);
            sts32(xl + p * SROW + jp * 4, lp);
        }
    }

    // ---- W staging (per tap) ----
    auto stageW = [&](int k) {
        for (int i = tid; i < OT * CP2; i += 256) {
            const int o = i / CP2, jp = i - o * CP2;
            u32 hp, lp;
            if (S == 1 && jp == 72) {          // const col: gdot + bias
                const float gv = d_g1w[b * 384 + k * 128 + (o0c + o)];
                split2(gv, 0.f, hp, lp);
            } else {
                const int src = (k * COUT + o0c + o) * CP2 + jp;
                hp = whsrc[src]; lp = wlsrc[src];
            }
            sts32(wh + o * SROW + jp * 4, hp);
            sts32(wl + o * SROW + jp * 4, lp);
        }
    };

    float acc[4][4];
#pragma unroll
    for (int nt = 0; nt < 4; nt++)
#pragma unroll
        for (int d = 0; d < 4; d++) acc[nt][d] = 0.f;

    const int arow = lid & 15, acol = (lid >> 4) * 16;
    const int brow = lid & 7,  bcol = ((lid >> 3) & 1) * 16;

    stageW(0);
    __syncthreads();
    for (int k = 0; k < 3; k++) {
#pragma unroll
        for (int kc = 0; kc < KC; kc++) {
            u32 Ah[4], Al[4];
            const u32 ab = xh + (wt * 16 + k + arow) * SROW + kc * 32 + acol;
            ldsm_x4(Ah, ab);
            ldsm_x4(Al, ab + XR * SROW);
#pragma unroll
            for (int nt = 0; nt < 4; nt++) {
                const u32 bb =
                    wh + (wo * 32 + nt * 8 + brow) * SROW + kc * 32 + bcol;
                u32 Bh[2], Bl[2];
                ldsm_x2(Bh, bb);
                ldsm_x2(Bl, bb + OT * SROW);
                mma_bf16(acc[nt], Ah, Bh);
                mma_bf16(acc[nt], Ah, Bl);
                mma_bf16(acc[nt], Al, Bh);
            }
        }
        if (k < 2) {
            __syncthreads();
            stageW(k + 1);
            __syncthreads();
        }
    }

    // ---- epilogue: bias, store, GN partial sums ----
    const int tt = t0 + wt * 16 + (lid >> 2);
    float* osum = d_osum + (S - 1) * NB * 128 + b * COUT;
    float* osq  = d_osq  + (S - 1) * NB * 128 + b * COUT;
#pragma unroll
    for (int nt = 0; nt < 4; nt++) {
        const int ob = wo * 32 + nt * 8 + (lid & 3) * 2;
        const int og = o0c + ob;
        float b0 = 0.f, b1 = 0.f;
        if constexpr (S > 1) { b0 = sb[ob]; b1 = sb[ob + 1]; }
        const float v00 = acc[nt][0] + b0, v01 = acc[nt][1] + b1;
        const float v10 = acc[nt][2] + b0, v11 = acc[nt][3] + b1;
        float* yp = &y[((size_t)b * COUT + og) * T_ + tt];
        yp[0] = v00; yp[8] = v10; yp[T_] = v01; yp[T_ + 8] = v11;

        float s0 = v00 + v10, q0 = fmaf(v00, v00, v10 * v10);
        float s1 = v01 + v11, q1 = fmaf(v01, v01, v11 * v11);
        s0 += __shfl_xor_sync(~0u, s0, 4);  q0 += __shfl_xor_sync(~0u, q0, 4);
        s0 += __shfl_xor_sync(~0u, s0, 8);  q0 += __shfl_xor_sync(~0u, q0, 8);
        s0 += __shfl_xor_sync(~0u, s0, 16); q0 += __shfl_xor_sync(~0u, q0, 16);
        s1 += __shfl_xor_sync(~0u, s1, 4);  q1 += __shfl_xor_sync(~0u, q1, 4);
        s1 += __shfl_xor_sync(~0u, s1, 8);  q1 += __shfl_xor_sync(~0u, q1, 8);
        s1 += __shfl_xor_sync(~0u, s1, 16); q1 += __shfl_xor_sync(~0u, q1, 16);
        if ((lid >> 2) == 0) {
            atomicAdd(&osum[og], s0);     atomicAdd(&osq[og], q0);
            atomicAdd(&osum[og + 1], s1); atomicAdd(&osq[og + 1], q1);
        }
    }
}

// ------------------------- GN finalize -------------------------------------
template <int S>
__global__ void __launch_bounds__(256) k_gnfin() {
    constexpr int COUT = (S == 1) ? C1 : (S == 2) ? C2 : C3;
    constexpr int CPG = COUT / 32;
    const int i = blockIdx.x * 256 + threadIdx.x;
    if (i >= NB * 32) return;
    const int b = i / 32, g = i % 32;
    const float* os = d_osum + (S - 1) * NB * 128 + b * COUT + g * CPG;
    const float* oq = d_osq  + (S - 1) * NB * 128 + b * COUT + g * CPG;
    float s = 0.f, q = 0.f;
#pragma unroll
    for (int j = 0; j < CPG; j++) { s += os[j]; q += oq[j]; }
    const float N = (float)(CPG * T_);
    const float m = s / N;
    d_meanA[(S - 1) * NB * 32 + i] = m;
    d_rstdA[(S - 1) * NB * 32 + i] = rsqrtf(q / N - m * m + 1e-5f);
}

// ------------------------- conv4 (k=1) + output affine ---------------------
__global__ void __launch_bounds__(256)
k_out(const float* __restrict__ w4, const float* __restrict__ b4,
      const float* __restrict__ s3, const float* __restrict__ bb3,
      const float* __restrict__ omean, const float* __restrict__ ostd,
      float* __restrict__ out) {
    const int b = blockIdx.y;
    const int t = blockIdx.x * 256 + threadIdx.x;
    __shared__ float A[32], Bc[32], W[32];
    if (threadIdx.x < 32) {
        const int c = threadIdx.x;
        const float a = d_rstdA[2 * NB * 32 + b * 32 + c] * s3[c];
        A[c] = a;
        Bc[c] = bb3[c] - d_meanA[2 * NB * 32 + b * 32 + c] * a;
        W[c] = w4[c];
    }
    __syncthreads();
    float acc = b4[0];
#pragma unroll
    for (int c = 0; c < 32; c++) {
        float v = d_y3[(b * 32 + c) * T_ + t];
        v = fmaxf(fmaf(v, A[c], Bc[c]), 0.f);
        acc = fmaf(W[c], v, acc);
    }
    out[(size_t)t * NB + b] = fmaf(acc, ostd[0], omean[0]);
}

// ------------------------- launch ------------------------------------------
constexpr int SROW1 = 336, SROW2 = 272, SROW3 = 144;
constexpr int SM1 = 2 * 66 * SROW1 + 2 * 64 * SROW1 + 512;    // ~87.9 KB
constexpr int SM2 = 2 * 66 * SROW2 + 2 * 64 * SROW2 + 2048;   // ~72.8 KB
constexpr int SM3 = 2 * 130 * SROW3 + 2 * 32 * SROW3 + 1024;  // ~47.7 KB

extern "C" void kernel_launch(void* const* d_in, const int* in_sizes, int n_in,
                              void* d_out, int out_size) {
    const float* input      = (const float*)d_in[0];
    const float* g_style    = (const float*)d_in[1];
    const float* char_style = (const float*)d_in[3];
    const float* c1w = (const float*)d_in[4];
    const float* c1b = (const float*)d_in[5];
    const float* g1s = (const float*)d_in[6];
    const float* g1b = (const float*)d_in[7];
    const float* c2w = (const float*)d_in[8];
    const float* c2b = (const float*)d_in[9];
    const float* g2s = (const float*)d_in[10];
    const float* g2b = (const float*)d_in[11];
    const float* c3w = (const float*)d_in[12];
    const float* c3b = (const float*)d_in[13];
    const float* g3s = (const float*)d_in[14];
    const float* g3b = (const float*)d_in[15];
    const float* c4w = (const float*)d_in[16];
    const float* c4b = (const float*)d_in[17];
    const float* om  = (const float*)d_in[18];
    const float* os  = (const float*)d_in[19];
    float* out = (float*)d_out;

    cudaFuncSetAttribute(k_cmma<1>, cudaFuncAttributeMaxDynamicSharedMemorySize, SM1);
    cudaFuncSetAttribute(k_cmma<2>, cudaFuncAttributeMaxDynamicSharedMemorySize, SM2);
    cudaFuncSetAttribute(k_cmma<3>, cudaFuncAttributeMaxDynamicSharedMemorySize, SM3);

    k_wprep<1><<<(3 * 128 * 80 + 255) / 256, 256>>>(c1w);      // 1
    k_wprep<2><<<(3 * 64 * 64 + 255) / 256, 256>>>(c2w);       // 2
    k_wprep<3><<<(3 * 32 * 32 + 255) / 256, 256>>>(c3w);       // 3
    k_amax<<<T_ * NB / 256, 256>>>(input);                     // 4 (+zero)
    k_gdot<<<NB, 384>>>(g_style, c1w, c1b);                    // 5

    k_cmma<1><<<dim3(16, 2, NB), 256, SM1>>>(input, char_style, nullptr); // 6
    k_gnfin<1><<<(NB * 32 + 255) / 256, 256>>>();

    k_cmma<2><<<dim3(16, 1, NB), 256, SM2>>>(g1s, g1b, c2b);
    k_gnfin<2><<<(NB * 32 + 255) / 256, 256>>>();

    k_cmma<3><<<dim3(8, 1, NB), 256, SM3>>>(g2s, g2b, c3b);
    k_gnfin<3><<<(NB * 32 + 255) / 256, 256>>>();

    k_out<<<dim3(T_ / 256, NB), 256>>>(c4w, c4b, g3s, g3b, om, os, out);
}

// round 16
// speedup vs baseline: 2.8175x; 1.4974x over previous
#include <cuda_runtime.h>
#include <cuda_fp16.h>
#include <cstdint>

// ---------------------------------------------------------------------------
// CharCountCNN — round 16 (= round 14 source, third attempt after two infra
// failures): warp-MMA convs in fp16 with 2-product hi/lo split
// (X split hi/lo, W single fp16; dropped term ~1e-4 rel). vs R13:
//   * MMA count -33%, W smem/staging halved -> 3/4/5 CTAs/SM
//   * launch order puts k_cmma<1> at slot #4 for ncu capture
// ---------------------------------------------------------------------------

using u32 = unsigned int;

constexpr int T_ = 1024, NB = 128, NCLS = 80, NSTY = 256;
constexpr int C1 = 128, C2 = 64, C3 = 32, CIN1W = 400;

// ------------------------- global scratch ----------------------------------
__device__ int   d_amax[NB * T_];                 // [t*NB + b]
__device__ float d_g1w[NB * 3 * C1];              // gdot + bias(k=1): [b][k][o]
__device__ float d_y1[NB * C1 * T_], d_y2[NB * C2 * T_], d_y3[NB * C3 * T_];
__device__ float d_osum[3 * NB * 128], d_osq[3 * NB * 128];
__device__ float d_meanA[3 * NB * 32], d_rstdA[3 * NB * 32];
// packed fp16-pair weight images [k][COUT][CP2] (hi only)
__device__ u32 d_w1u[3 * 128 * 80];   // cols 0..159
__device__ u32 d_w2u[3 * 64 * 64];    // cols 0..127
__device__ u32 d_w3u[3 * 32 * 32];    // cols 0..63

// ------------------------- helpers -----------------------------------------
__device__ __forceinline__ u32 smem_u32(const void* p) {
    u32 a;
    asm("{ .reg .u64 t; cvta.to.shared.u64 t, %1; cvt.u32.u64 %0, t; }"
        : "=r"(a) : "l"(p));
    return a;
}
__device__ __forceinline__ void sts32(u32 a, u32 v) {
    asm volatile("st.shared.u32 [%0], %1;" :: "r"(a), "r"(v) : "memory");
}
__device__ __forceinline__ void ldsm_x4(u32* r, u32 a) {
    asm volatile("ldmatrix.sync.aligned.m8n8.x4.shared.b16 {%0,%1,%2,%3}, [%4];"
                 : "=r"(r[0]), "=r"(r[1]), "=r"(r[2]), "=r"(r[3]) : "r"(a));
}
__device__ __forceinline__ void ldsm_x2(u32* r, u32 a) {
    asm volatile("ldmatrix.sync.aligned.m8n8.x2.shared.b16 {%0,%1}, [%2];"
                 : "=r"(r[0]), "=r"(r[1]) : "r"(a));
}
__device__ __forceinline__ void mma_f16(float* d, const u32* A, const u32* B) {
    asm volatile(
        "mma.sync.aligned.m16n8k16.row.col.f32.f16.f16.f32 "
        "{%0,%1,%2,%3}, {%4,%5,%6,%7}, {%8,%9}, {%0,%1,%2,%3};"
        : "+f"(d[0]), "+f"(d[1]), "+f"(d[2]), "+f"(d[3])
        : "r"(A[0]), "r"(A[1]), "r"(A[2]), "r"(A[3]), "r"(B[0]), "r"(B[1]));
}
__device__ __forceinline__ u32 packH2(float v0, float v1) {
    __half2 h = __floats2half2_rn(v0, v1);
    return *reinterpret_cast<u32*>(&h);
}
// X split: hi + lo fp16 pairs
__device__ __forceinline__ void splitH2(float v0, float v1, u32& hp, u32& lp) {
    const __half h0 = __float2half_rn(v0), h1 = __float2half_rn(v1);
    const float r0 = v0 - __half2float(h0), r1 = v1 - __half2float(h1);
    __half2 hh = __halves2half2(h0, h1);
    __half2 ll = __floats2half2_rn(r0, r1);
    hp = *reinterpret_cast<u32*>(&hh);
    lp = *reinterpret_cast<u32*>(&ll);
}

// ------------------------- argmax (+ zero GN accumulators) -----------------
__global__ void __launch_bounds__(256) k_amax(const float* __restrict__ inp) {
    const int r = blockIdx.x * 256 + threadIdx.x;   // r = t*NB + b
    if (r < 3 * NB * 128) { d_osum[r] = 0.f; d_osq[r] = 0.f; }
    const float4* row = reinterpret_cast<const float4*>(inp + (size_t)r * NCLS);
    float best = -3.4e38f;
    int bi = 0;
#pragma unroll
    for (int c4 = 0; c4 < NCLS / 4; c4++) {
        float4 v = row[c4];
        int c = c4 * 4;
        if (v.x > best) { best = v.x; bi = c + 0; }
        if (v.y > best) { best = v.y; bi = c + 1; }
        if (v.z > best) { best = v.z; bi = c + 2; }
        if (v.w > best) { best = v.w; bi = c + 3; }
    }
    d_amax[r] = bi;
}

// ------------------------- weight prep (all stages, one launch) ------------
constexpr int NW1 = 3 * 128 * 80, NW2 = 3 * 64 * 64, NW3 = 3 * 32 * 32;
__global__ void __launch_bounds__(256)
k_wprep(const float* __restrict__ w1, const float* __restrict__ w2,
        const float* __restrict__ w3) {
    const int i = blockIdx.x * 256 + threadIdx.x;
    if (i < NW1) {
        const int jp = i % 80, o = (i / 80) % 128, k = i / (80 * 128);
        auto val = [&](int c) -> float {
            if (c < 80)  return w1[(o * CIN1W + c) * 3 + k];
            if (c < 144) return w1[(o * CIN1W + 336 + (c - 80)) * 3 + k];
            return 0.f;
        };
        d_w1u[i] = packH2(val(2 * jp), val(2 * jp + 1));
    } else if (i < NW1 + NW2) {
        const int j = i - NW1;
        const int jp = j % 64, o = (j / 64) % 64, k = j / (64 * 64);
        d_w2u[j] = packH2(w2[(o * C1 + 2 * jp) * 3 + k],
                          w2[(o * C1 + 2 * jp + 1) * 3 + k]);
    } else if (i < NW1 + NW2 + NW3) {
        const int j = i - NW1 - NW2;
        const int jp = j % 32, o = (j / 32) % 32, k = j / (32 * 32);
        d_w3u[j] = packH2(w3[(o * C2 + 2 * jp) * 3 + k],
                          w3[(o * C2 + 2 * jp + 1) * 3 + k]);
    }
}

// ------------------------- gdot (+bias at k=1) -----------------------------
__global__ void __launch_bounds__(384) k_gdot(const float* __restrict__ g_style,
                                              const float* __restrict__ w1,
                                              const float* __restrict__ b1) {
    __shared__ float gs[NSTY];
    const int b = blockIdx.x, tid = threadIdx.x;
    for (int c = tid; c < NSTY; c += 384) gs[c] = g_style[b * NSTY + c];
    __syncthreads();
    const int o = tid / 3, k = tid % 3;
    const float* wp = w1 + o * (CIN1W * 3) + NCLS * 3 + k;
    float acc = (k == 1) ? b1[o] : 0.f;
#pragma unroll 8
    for (int c = 0; c < NSTY; c++) acc = fmaf(gs[c], wp[c * 3], acc);
    d_g1w[b * 384 + k * 128 + o] = acc;
}

// ------------------------- conv via warp MMA -------------------------------
// 256 threads. grid (T_/TT, COUT/OT, NB).
template <int S>
__global__ void __launch_bounds__(256)
k_cmma(const float* __restrict__ p0a, const float* __restrict__ p1a,
       const float* __restrict__ p2a) {
    constexpr int CIN  = (S == 1) ? 80 : (S == 2) ? C1 : C2;
    constexpr int COUT = (S == 1) ? C1 : (S == 2) ? C2 : C3;
    constexpr int CPAD = (S == 1) ? 160 : (S == 2) ? 128 : 64;
    constexpr int CP2  = CPAD / 2;
    constexpr int SROW = CPAD * 2 + 16;
    constexpr int KC   = CPAD / 16;
    constexpr int TT   = (S == 3) ? 128 : 64;
    constexpr int OT   = (S == 3) ? 32 : 64;
    constexpr int WT   = (S == 3) ? 8 : 4;      // warps along t
    constexpr int XR   = TT + 2;

    const float* xprev = (S == 2) ? d_y1 : d_y2;   // S==3 uses d_y2
    float* y = (S == 1) ? d_y1 : (S == 2) ? d_y2 : d_y3;
    const u32* wsrc = (S == 1) ? d_w1u : (S == 2) ? d_w2u : d_w3u;

    extern __shared__ char dynsm[];
    const u32 sraw = smem_u32(dynsm);
    const u32 sbA = (sraw + 127) & ~127u;
    char* bp = dynsm + (sbA - sraw);
    const u32 xh = sbA, xl = xh + XR * SROW;
    const u32 wh = xl + XR * SROW;
    char* auxp = bp + 2 * XR * SROW + OT * SROW;
    int*   sam = (int*)auxp;              // S1
    float* gA  = (float*)auxp;            // S>1
    float* gB  = gA + CIN;
    float* sb  = gB + CIN;

    const int b = blockIdx.z, t0 = blockIdx.x * TT, o0c = blockIdx.y * OT;
    const int tid = threadIdx.x, wid = tid >> 5, lid = tid & 31;
    const int wt = wid % WT, wo = wid / WT;

    // ---- aux staging ----
    if constexpr (S == 1) {
        for (int p = tid; p < XR; p += 256) {
            const int t = t0 - 1 + p;
            sam[p] = (t >= 0 && t < T_) ? d_amax[t * NB + b] : 0;
        }
    } else {
        const float* pm = d_meanA + (S - 2) * NB * 32;
        const float* pr = d_rstdA + (S - 2) * NB * 32;
        for (int c = tid; c < CIN; c += 256) {
            const int g = c / (CIN / 32);
            const float a = pr[b * 32 + g] * p0a[c];      // gns
            gA[c] = a;
            gB[c] = p1a[c] - pm[b * 32 + g] * a;          // gnb
        }
        for (int i = tid; i < OT; i += 256) sb[i] = p2a[o0c + i];   // bias
    }
    __syncthreads();

    // ---- X staging (hi/lo fp16 split) ----
    if constexpr (S == 1) {
        for (int i = tid; i < XR * CP2; i += 256) {
            const int p = i / CP2, jp = i - p * CP2;
            const int t = t0 - 1 + p;
            const int c0 = 2 * jp;
            float v0 = 0.f, v1 = 0.f;
            if (t >= 0 && t < T_) {
                if (c0 < 80) {
                    const float* ip = p0a + ((size_t)t * NB + b) * NCLS + c0;
                    v0 = ip[0]; v1 = ip[1];
                } else if (c0 < 144) {
                    const float* cp =
                        p1a + ((size_t)b * NCLS + sam[p]) * 64 + (c0 - 80);
                    v0 = cp[0]; v1 = cp[1];
                } else if (c0 == 144) {
                    v0 = 1.f;
                }
            }
            u32 hp, lp;
            splitH2(v0, v1, hp, lp);
            sts32(xh + p * SROW + jp * 4, hp);
            sts32(xl + p * SROW + jp * 4, lp);
        }
    } else {
        for (int i = tid; i < CP2 * XR; i += 256) {
            const int jp = i / XR, p = i - jp * XR;
            const int t = t0 - 1 + p;
            const int c0 = 2 * jp;
            float v0 = 0.f, v1 = 0.f;
            if (t >= 0 && t < T_) {
                const float a0 = xprev[((size_t)b * CIN + c0) * T_ + t];
                const float a1 = xprev[((size_t)b * CIN + c0 + 1) * T_ + t];
                v0 = fmaxf(fmaf(a0, gA[c0], gB[c0]), 0.f);
                v1 = fmaxf(fmaf(a1, gA[c0 + 1], gB[c0 + 1]), 0.f);
            }
            u32 hp, lp;
            splitH2(v0, v1, hp, lp);
            sts32(xh + p * SROW + jp * 4, hp);
            sts32(xl + p * SROW + jp * 4, lp);
        }
    }

    // ---- W staging (per tap, single fp16 image) ----
    auto stageW = [&](int k) {
        for (int i = tid; i < OT * CP2; i += 256) {
            const int o = i / CP2, jp = i - o * CP2;
            u32 hp;
            if (S == 1 && jp == 72) {          // const col: gdot + bias
                hp = packH2(d_g1w[b * 384 + k * 128 + (o0c + o)], 0.f);
            } else {
                hp = wsrc[(k * COUT + o0c + o) * CP2 + jp];
            }
            sts32(wh + o * SROW + jp * 4, hp);
        }
    };

    float acc[4][4];
#pragma unroll
    for (int nt = 0; nt < 4; nt++)
#pragma unroll
        for (int d = 0; d < 4; d++) acc[nt][d] = 0.f;

    const int arow = lid & 15, acol = (lid >> 4) * 16;
    const int brow = lid & 7,  bcol = ((lid >> 3) & 1) * 16;

    stageW(0);
    __syncthreads();
    for (int k = 0; k < 3; k++) {
#pragma unroll
        for (int kc = 0; kc < KC; kc++) {
            u32 Ah[4], Al[4];
            const u32 ab = xh + (wt * 16 + k + arow) * SROW + kc * 32 + acol;
            ldsm_x4(Ah, ab);
            ldsm_x4(Al, ab + XR * SROW);
#pragma unroll
            for (int nt = 0; nt < 4; nt++) {
                const u32 bb =
                    wh + (wo * 32 + nt * 8 + brow) * SROW + kc * 32 + bcol;
                u32 Bh[2];
                ldsm_x2(Bh, bb);
                mma_f16(acc[nt], Ah, Bh);
                mma_f16(acc[nt], Al, Bh);
            }
        }
        if (k < 2) {
            __syncthreads();
            stageW(k + 1);
            __syncthreads();
        }
    }

    // ---- epilogue: bias, store, GN partial sums ----
    const int tt = t0 + wt * 16 + (lid >> 2);
    float* osum = d_osum + (S - 1) * NB * 128 + b * COUT;
    float* osq  = d_osq  + (S - 1) * NB * 128 + b * COUT;
#pragma unroll
    for (int nt = 0; nt < 4; nt++) {
        const int ob = wo * 32 + nt * 8 + (lid & 3) * 2;
        const int og = o0c + ob;
        float b0 = 0.f, b1 = 0.f;
        if constexpr (S > 1) { b0 = sb[ob]; b1 = sb[ob + 1]; }
        const float v00 = acc[nt][0] + b0, v01 = acc[nt][1] + b1;
        const float v10 = acc[nt][2] + b0, v11 = acc[nt][3] + b1;
        float* yp = &y[((size_t)b * COUT + og) * T_ + tt];
        yp[0] = v00; yp[8] = v10; yp[T_] = v01; yp[T_ + 8] = v11;

        float s0 = v00 + v10, q0 = fmaf(v00, v00, v10 * v10);
        float s1 = v01 + v11, q1 = fmaf(v01, v01, v11 * v11);
        s0 += __shfl_xor_sync(~0u, s0, 4);  q0 += __shfl_xor_sync(~0u, q0, 4);
        s0 += __shfl_xor_sync(~0u, s0, 8);  q0 += __shfl_xor_sync(~0u, q0, 8);
        s0 += __shfl_xor_sync(~0u, s0, 16); q0 += __shfl_xor_sync(~0u, q0, 16);
        s1 += __shfl_xor_sync(~0u, s1, 4);  q1 += __shfl_xor_sync(~0u, q1, 4);
        s1 += __shfl_xor_sync(~0u, s1, 8);  q1 += __shfl_xor_sync(~0u, q1, 8);
        s1 += __shfl_xor_sync(~0u, s1, 16); q1 += __shfl_xor_sync(~0u, q1, 16);
        if ((lid >> 2) == 0) {
            atomicAdd(&osum[og], s0);     atomicAdd(&osq[og], q0);
            atomicAdd(&osum[og + 1], s1); atomicAdd(&osq[og + 1], q1);
        }
    }
}

// ------------------------- GN finalize -------------------------------------
template <int S>
__global__ void __launch_bounds__(256) k_gnfin() {
    constexpr int COUT = (S == 1) ? C1 : (S == 2) ? C2 : C3;
    constexpr int CPG = COUT / 32;
    const int i = blockIdx.x * 256 + threadIdx.x;
    if (i >= NB * 32) return;
    const int b = i / 32, g = i % 32;
    const float* os = d_osum + (S - 1) * NB * 128 + b * COUT + g * CPG;
    const float* oq = d_osq  + (S - 1) * NB * 128 + b * COUT + g * CPG;
    float s = 0.f, q = 0.f;
#pragma unroll
    for (int j = 0; j < CPG; j++) { s += os[j]; q += oq[j]; }
    const float N = (float)(CPG * T_);
    const float m = s / N;
    d_meanA[(S - 1) * NB * 32 + i] = m;
    d_rstdA[(S - 1) * NB * 32 + i] = rsqrtf(q / N - m * m + 1e-5f);
}

// ------------------------- conv4 (k=1) + output affine ---------------------
__global__ void __launch_bounds__(256)
k_out(const float* __restrict__ w4, const float* __restrict__ b4,
      const float* __restrict__ s3, const float* __restrict__ bb3,
      const float* __restrict__ omean, const float* __restrict__ ostd,
      float* __restrict__ out) {
    const int b = blockIdx.y;
    const int t = blockIdx.x * 256 + threadIdx.x;
    __shared__ float A[32], Bc[32], W[32];
    if (threadIdx.x < 32) {
        const int c = threadIdx.x;
        const float a = d_rstdA[2 * NB * 32 + b * 32 + c] * s3[c];
        A[c] = a;
        Bc[c] = bb3[c] - d_meanA[2 * NB * 32 + b * 32 + c] * a;
        W[c] = w4[c];
    }
    __syncthreads();
    float acc = b4[0];
#pragma unroll
    for (int c = 0; c < 32; c++) {
        float v = d_y3[(b * 32 + c) * T_ + t];
        v = fmaxf(fmaf(v, A[c], Bc[c]), 0.f);
        acc = fmaf(W[c], v, acc);
    }
    out[(size_t)t * NB + b] = fmaf(acc, ostd[0], omean[0]);
}

// ------------------------- launch ------------------------------------------
constexpr int SROW1 = 336, SROW2 = 272, SROW3 = 144;
constexpr int SM1 = 2 * 66 * SROW1 + 64 * SROW1 + 512;     // ~66.4 KB
constexpr int SM2 = 2 * 66 * SROW2 + 64 * SROW2 + 2048;    // ~55.4 KB
constexpr int SM3 = 2 * 130 * SROW3 + 32 * SROW3 + 1024;   // ~43.1 KB

extern "C" void kernel_launch(void* const* d_in, const int* in_sizes, int n_in,
                              void* d_out, int out_size) {
    const float* input      = (const float*)d_in[0];
    const float* g_style    = (const float*)d_in[1];
    const float* char_style = (const float*)d_in[3];
    const float* c1w = (const float*)d_in[4];
    const float* c1b = (const float*)d_in[5];
    const float* g1s = (const float*)d_in[6];
    const float* g1b = (const float*)d_in[7];
    const float* c2w = (const float*)d_in[8];
    const float* c2b = (const float*)d_in[9];
    const float* g2s = (const float*)d_in[10];
    const float* g2b = (const float*)d_in[11];
    const float* c3w = (const float*)d_in[12];
    const float* c3b = (const float*)d_in[13];
    const float* g3s = (const float*)d_in[14];
    const float* g3b = (const float*)d_in[15];
    const float* c4w = (const float*)d_in[16];
    const float* c4b = (const float*)d_in[17];
    const float* om  = (const float*)d_in[18];
    const float* os  = (const float*)d_in[19];
    float* out = (float*)d_out;

    cudaFuncSetAttribute(k_cmma<1>, cudaFuncAttributeMaxDynamicSharedMemorySize, SM1);
    cudaFuncSetAttribute(k_cmma<2>, cudaFuncAttributeMaxDynamicSharedMemorySize, SM2);
    cudaFuncSetAttribute(k_cmma<3>, cudaFuncAttributeMaxDynamicSharedMemorySize, SM3);

    k_amax<<<T_ * NB / 256, 256>>>(input);                              // 1
    k_wprep<<<(NW1 + NW2 + NW3 + 255) / 256, 256>>>(c1w, c2w, c3w);     // 2
    k_gdot<<<NB, 384>>>(g_style, c1w, c1b);                             // 3

    k_cmma<1><<<dim3(16, 2, NB), 256, SM1>>>(input, char_style, nullptr); // 4
    k_gnfin<1><<<(NB * 32 + 255) / 256, 256>>>();

    k_cmma<2><<<dim3(16, 1, NB), 256, SM2>>>(g1s, g1b, c2b);
    k_gnfin<2><<<(NB * 32 + 255) / 256, 256>>>();

    k_cmma<3><<<dim3(8, 1, NB), 256, SM3>>>(g2s, g2b, c3b);
    k_gnfin<3><<<(NB * 32 + 255) / 256, 256>>>();

    k_out<<<dim3(T_ / 256, NB), 256>>>(c4w, c4b, g3s, g3b, om, os, out);
}

// round 17
// speedup vs baseline: 2.8884x; 1.0252x over previous
#include <cuda_runtime.h>
#include <cuda_fp16.h>
#include <cstdint>

// ---------------------------------------------------------------------------
// CharCountCNN — round 17: fp16 2-product warp-MMA convs; S1 shrunk:
//   * char_style contribution moved OUT of the GEMM into a precomputed
//     sdot[b][ch][k][o] table added in the epilogue (K 480 -> 288, exact fp32)
//   * S1 tile 64t x 128o, X staged once (was twice), CPAD=96
//   * amax+wprep merged so k_cmma<1> stays at ncu capture slot 4
// ---------------------------------------------------------------------------

using u32 = unsigned int;

constexpr int T_ = 1024, NB = 128, NCLS = 80, NSTY = 256;
constexpr int C1 = 128, C2 = 64, C3 = 32, CIN1W = 400;

// ------------------------- global scratch ----------------------------------
__device__ int   d_amax[NB * T_];                 // [t*NB + b]
__device__ float d_g1w[NB * 3 * C1];              // gdot + bias(k=1): [b][k][o]
__device__ float d_sdot[NB * NCLS * 3 * C1];      // [b][ch][k*128+o]
__device__ float d_y1[NB * C1 * T_], d_y2[NB * C2 * T_], d_y3[NB * C3 * T_];
__device__ float d_osum[3 * NB * 128], d_osq[3 * NB * 128];
__device__ float d_meanA[3 * NB * 32], d_rstdA[3 * NB * 32];
// packed fp16-pair weight images [k][COUT][CP2]
__device__ u32 d_w1u[3 * 128 * 48];   // cols 0..95 (80 input + const + pad)
__device__ u32 d_w2u[3 * 64 * 64];    // cols 0..127
__device__ u32 d_w3u[3 * 32 * 32];    // cols 0..63

// ------------------------- helpers -----------------------------------------
__device__ __forceinline__ u32 smem_u32(const void* p) {
    u32 a;
    asm("{ .reg .u64 t; cvta.to.shared.u64 t, %1; cvt.u32.u64 %0, t; }"
        : "=r"(a) : "l"(p));
    return a;
}
__device__ __forceinline__ void sts32(u32 a, u32 v) {
    asm volatile("st.shared.u32 [%0], %1;" :: "r"(a), "r"(v) : "memory");
}
__device__ __forceinline__ void ldsm_x4(u32* r, u32 a) {
    asm volatile("ldmatrix.sync.aligned.m8n8.x4.shared.b16 {%0,%1,%2,%3}, [%4];"
                 : "=r"(r[0]), "=r"(r[1]), "=r"(r[2]), "=r"(r[3]) : "r"(a));
}
__device__ __forceinline__ void ldsm_x2(u32* r, u32 a) {
    asm volatile("ldmatrix.sync.aligned.m8n8.x2.shared.b16 {%0,%1}, [%2];"
                 : "=r"(r[0]), "=r"(r[1]) : "r"(a));
}
__device__ __forceinline__ void mma_f16(float* d, const u32* A, const u32* B) {
    asm volatile(
        "mma.sync.aligned.m16n8k16.row.col.f32.f16.f16.f32 "
        "{%0,%1,%2,%3}, {%4,%5,%6,%7}, {%8,%9}, {%0,%1,%2,%3};"
        : "+f"(d[0]), "+f"(d[1]), "+f"(d[2]), "+f"(d[3])
        : "r"(A[0]), "r"(A[1]), "r"(A[2]), "r"(A[3]), "r"(B[0]), "r"(B[1]));
}
__device__ __forceinline__ u32 packH2(float v0, float v1) {
    __half2 h = __floats2half2_rn(v0, v1);
    return *reinterpret_cast<u32*>(&h);
}
__device__ __forceinline__ void splitH2(float v0, float v1, u32& hp, u32& lp) {
    const __half h0 = __float2half_rn(v0), h1 = __float2half_rn(v1);
    const float r0 = v0 - __half2float(h0), r1 = v1 - __half2float(h1);
    __half2 hh = __halves2half2(h0, h1);
    __half2 ll = __floats2half2_rn(r0, r1);
    hp = *reinterpret_cast<u32*>(&hh);
    lp = *reinterpret_cast<u32*>(&ll);
}

// ------------------------- prep: argmax + zero + weight images -------------
constexpr int NW1 = 3 * 128 * 48, NW2 = 3 * 64 * 64, NW3 = 3 * 32 * 32;
__global__ void __launch_bounds__(256)
k_prep0(const float* __restrict__ inp, const float* __restrict__ w1,
        const float* __restrict__ w2, const float* __restrict__ w3) {
    const int r = blockIdx.x * 256 + threadIdx.x;   // r = t*NB + b
    if (r < 3 * NB * 128) { d_osum[r] = 0.f; d_osq[r] = 0.f; }
    // weight images
    if (r < NW1) {
        const int jp = r % 48, o = (r / 48) % 128, k = r / (48 * 128);
        auto val = [&](int c) -> float {
            return (c < 80) ? w1[(o * CIN1W + c) * 3 + k] : 0.f;
        };
        d_w1u[r] = packH2(val(2 * jp), val(2 * jp + 1));
    } else if (r < NW1 + NW2) {
        const int j = r - NW1;
        const int jp = j % 64, o = (j / 64) % 64, k = j / (64 * 64);
        d_w2u[j] = packH2(w2[(o * C1 + 2 * jp) * 3 + k],
                          w2[(o * C1 + 2 * jp + 1) * 3 + k]);
    } else if (r < NW1 + NW2 + NW3) {
        const int j = r - NW1 - NW2;
        const int jp = j % 32, o = (j / 32) % 32, k = j / (32 * 32);
        d_w3u[j] = packH2(w3[(o * C2 + 2 * jp) * 3 + k],
                          w3[(o * C2 + 2 * jp + 1) * 3 + k]);
    }
    // argmax
    const float4* row = reinterpret_cast<const float4*>(inp + (size_t)r * NCLS);
    float best = -3.4e38f;
    int bi = 0;
#pragma unroll
    for (int c4 = 0; c4 < NCLS / 4; c4++) {
        float4 v = row[c4];
        int c = c4 * 4;
        if (v.x > best) { best = v.x; bi = c + 0; }
        if (v.y > best) { best = v.y; bi = c + 1; }
        if (v.z > best) { best = v.z; bi = c + 2; }
        if (v.w > best) { best = v.w; bi = c + 3; }
    }
    d_amax[r] = bi;
}

// ------------------------- gdot (+bias at k=1) -----------------------------
__global__ void __launch_bounds__(384) k_gdot(const float* __restrict__ g_style,
                                              const float* __restrict__ w1,
                                              const float* __restrict__ b1) {
    __shared__ float gs[NSTY];
    const int b = blockIdx.x, tid = threadIdx.x;
    for (int c = tid; c < NSTY; c += 384) gs[c] = g_style[b * NSTY + c];
    __syncthreads();
    const int o = tid / 3, k = tid % 3;
    const float* wp = w1 + o * (CIN1W * 3) + NCLS * 3 + k;
    float acc = (k == 1) ? b1[o] : 0.f;
#pragma unroll 8
    for (int c = 0; c < NSTY; c++) acc = fmaf(gs[c], wp[c * 3], acc);
    d_g1w[b * 384 + k * 128 + o] = acc;
}

// ------------------------- sdot table: [b][ch][k*128+o] --------------------
// grid NB, block 256, dyn smem: ws[64*384] + cs[80*64]
__global__ void __launch_bounds__(256)
k_sdot(const float* __restrict__ char_style, const float* __restrict__ w1) {
    extern __shared__ float sm[];
    float* ws = sm;               // ws[c][k*128+o]
    float* cs = sm + 64 * 384;    // cs[ch][c]
    const int b = blockIdx.x, tid = threadIdx.x;
    for (int i = tid; i < 64 * 384; i += 256) {
        const int c = i / 384, r = i % 384, k = r / 128, o = r % 128;
        ws[i] = w1[(o * CIN1W + 336 + c) * 3 + k];
    }
    for (int i = tid; i < 80 * 64; i += 256)
        cs[i] = char_style[(size_t)b * 5120 + i];
    __syncthreads();
    for (int i = tid; i < 80 * 96; i += 256) {
        const int ch = i / 96, q = i % 96;
        const float* cc = cs + ch * 64;
        float4 acc = make_float4(0.f, 0.f, 0.f, 0.f);
#pragma unroll 8
        for (int c = 0; c < 64; c++) {
            const float4 wv = *reinterpret_cast<const float4*>(ws + c * 384 + q * 4);
            const float cv = cc[c];
            acc.x = fmaf(cv, wv.x, acc.x);
            acc.y = fmaf(cv, wv.y, acc.y);
            acc.z = fmaf(cv, wv.z, acc.z);
            acc.w = fmaf(cv, wv.w, acc.w);
        }
        *reinterpret_cast<float4*>(d_sdot + (size_t)b * 80 * 384 + ch * 384 + q * 4) = acc;
    }
}

// ------------------------- conv via warp MMA -------------------------------
// 256 threads. grid (T_/TT, NB).
template <int S>
__global__ void __launch_bounds__(256)
k_cmma(const float* __restrict__ p0a, const float* __restrict__ p1a,
       const float* __restrict__ p2a) {
    constexpr int CIN  = (S == 1) ? 80 : (S == 2) ? C1 : C2;
    constexpr int COUT = (S == 1) ? C1 : (S == 2) ? C2 : C3;
    constexpr int CPAD = (S == 1) ? 96 : (S == 2) ? 128 : 64;
    constexpr int CP2  = CPAD / 2;
    constexpr int SROW = CPAD * 2 + 16;
    constexpr int KC   = CPAD / 16;
    constexpr int TT   = (S == 3) ? 128 : 64;
    constexpr int OT   = (S == 1) ? 128 : (S == 2) ? 64 : 32;
    constexpr int WT   = (S == 3) ? 8 : 4;      // warps along t
    constexpr int WO   = (S == 3) ? 1 : 2;      // warps along o
    constexpr int NT   = OT / (8 * WO);         // 8 / 4 / 4
    constexpr int OSPAN = NT * 8;               // o's per warp
    constexpr int XR   = TT + 2;

    const float* xprev = (S == 2) ? d_y1 : d_y2;   // S==3 uses d_y2
    float* y = (S == 1) ? d_y1 : (S == 2) ? d_y2 : d_y3;
    const u32* wsrc = (S == 1) ? d_w1u : (S == 2) ? d_w2u : d_w3u;

    extern __shared__ char dynsm[];
    const u32 sraw = smem_u32(dynsm);
    const u32 sbA = (sraw + 127) & ~127u;
    char* bp = dynsm + (sbA - sraw);
    const u32 xh = sbA, xl = xh + XR * SROW;
    const u32 wh = xl + XR * SROW;
    char* auxp = bp + 2 * XR * SROW + OT * SROW;
    int*   sam = (int*)auxp;              // S1
    float* gA  = (float*)auxp;            // S>1
    float* gB  = gA + CIN;
    float* sb  = gB + CIN;

    const int b = blockIdx.y, t0 = blockIdx.x * TT;
    const int tid = threadIdx.x, wid = tid >> 5, lid = tid & 31;
    const int wt = wid % WT, wo = wid / WT;

    // ---- aux staging ----
    if constexpr (S == 1) {
        for (int p = tid; p < XR; p += 256) {
            const int t = t0 - 1 + p;
            sam[p] = (t >= 0 && t < T_) ? d_amax[t * NB + b] : 0;
        }
    } else {
        const float* pm = d_meanA + (S - 2) * NB * 32;
        const float* pr = d_rstdA + (S - 2) * NB * 32;
        for (int c = tid; c < CIN; c += 256) {
            const int g = c / (CIN / 32);
            const float a = pr[b * 32 + g] * p0a[c];      // gns
            gA[c] = a;
            gB[c] = p1a[c] - pm[b * 32 + g] * a;          // gnb
        }
        for (int i = tid; i < OT; i += 256) sb[i] = p2a[i];   // bias
    }
    __syncthreads();

    // ---- X staging (hi/lo fp16 split) ----
    if constexpr (S == 1) {
        for (int i = tid; i < XR * CP2; i += 256) {
            const int p = i / CP2, jp = i - p * CP2;
            const int t = t0 - 1 + p;
            const int c0 = 2 * jp;
            float v0 = 0.f, v1 = 0.f;
            if (t >= 0 && t < T_) {
                if (c0 < 80) {
                    const float* ip = p0a + ((size_t)t * NB + b) * NCLS + c0;
                    v0 = ip[0]; v1 = ip[1];
                } else if (c0 == 80) {
                    v0 = 1.f;     // const channel (gdot + bias)
                }
            }
            u32 hp, lp;
            splitH2(v0, v1, hp, lp);
            sts32(xh + p * SROW + jp * 4, hp);
            sts32(xl + p * SROW + jp * 4, lp);
        }
    } else {
        for (int i = tid; i < CP2 * XR; i += 256) {
            const int jp = i / XR, p = i - jp * XR;
            const int t = t0 - 1 + p;
            const int c0 = 2 * jp;
            float v0 = 0.f, v1 = 0.f;
            if (t >= 0 && t < T_) {
                const float a0 = xprev[((size_t)b * CIN + c0) * T_ + t];
                const float a1 = xprev[((size_t)b * CIN + c0 + 1) * T_ + t];
                v0 = fmaxf(fmaf(a0, gA[c0], gB[c0]), 0.f);
                v1 = fmaxf(fmaf(a1, gA[c0 + 1], gB[c0 + 1]), 0.f);
            }
            u32 hp, lp;
            splitH2(v0, v1, hp, lp);
            sts32(xh + p * SROW + jp * 4, hp);
            sts32(xl + p * SROW + jp * 4, lp);
        }
    }

    // ---- W staging (per tap) ----
    auto stageW = [&](int k) {
        for (int i = tid; i < OT * CP2; i += 256) {
            const int o = i / CP2, jp = i - o * CP2;
            u32 hp;
            if (S == 1 && jp == 40) {          // const col: gdot + bias
                hp = packH2(d_g1w[b * 384 + k * 128 + o], 0.f);
            } else {
                hp = wsrc[(k * COUT + o) * CP2 + jp];
            }
            sts32(wh + o * SROW + jp * 4, hp);
        }
    };

    float acc[NT][4];
#pragma unroll
    for (int nt = 0; nt < NT; nt++)
#pragma unroll
        for (int d = 0; d < 4; d++) acc[nt][d] = 0.f;

    const int arow = lid & 15, acol = (lid >> 4) * 16;
    const int brow = lid & 7,  bcol = ((lid >> 3) & 1) * 16;

    stageW(0);
    __syncthreads();
    for (int k = 0; k < 3; k++) {
#pragma unroll
        for (int kc = 0; kc < KC; kc++) {
            u32 Ah[4], Al[4];
            const u32 ab = xh + (wt * 16 + k + arow) * SROW + kc * 32 + acol;
            ldsm_x4(Ah, ab);
            ldsm_x4(Al, ab + XR * SROW);
#pragma unroll
            for (int nt = 0; nt < NT; nt++) {
                const u32 bb =
                    wh + (wo * OSPAN + nt * 8 + brow) * SROW + kc * 32 + bcol;
                u32 Bh[2];
                ldsm_x2(Bh, bb);
                mma_f16(acc[nt], Ah, Bh);
                mma_f16(acc[nt], Al, Bh);
            }
        }
        if (k < 2) {
            __syncthreads();
            stageW(k + 1);
            __syncthreads();
        }
    }

    // ---- epilogue: bias/sdot, store, GN partial sums ----
    const int tl0 = wt * 16 + (lid >> 2);
    const int tt = t0 + tl0;
    float* osum = d_osum + (S - 1) * NB * 128 + b * COUT;
    float* osq  = d_osq  + (S - 1) * NB * 128 + b * COUT;
    const float* sd = d_sdot + (size_t)b * 80 * 384;
#pragma unroll
    for (int nt = 0; nt < NT; nt++) {
        const int og = wo * OSPAN + nt * 8 + (lid & 3) * 2;
        float b0 = 0.f, b1 = 0.f;
        if constexpr (S > 1) { b0 = sb[og]; b1 = sb[og + 1]; }
        float v00 = acc[nt][0] + b0, v01 = acc[nt][1] + b1;
        float v10 = acc[nt][2] + b0, v11 = acc[nt][3] + b1;
        if constexpr (S == 1) {
            // row 0: t = tt
            {
                const int tl = tl0;
                float2 f1 = *(const float2*)(sd + sam[tl + 1] * 384 + 128 + og);
                v00 += f1.x; v01 += f1.y;
                if (tt > 0) {
                    float2 f0 = *(const float2*)(sd + sam[tl] * 384 + og);
                    v00 += f0.x; v01 += f0.y;
                }
                if (tt < T_ - 1) {
                    float2 f2 = *(const float2*)(sd + sam[tl + 2] * 384 + 256 + og);
                    v00 += f2.x; v01 += f2.y;
                }
            }
            // row 1: t = tt + 8
            {
                const int tl = tl0 + 8;
                const int t = tt + 8;
                float2 f1 = *(const float2*)(sd + sam[tl + 1] * 384 + 128 + og);
                v10 += f1.x; v11 += f1.y;
                if (t > 0) {
                    float2 f0 = *(const float2*)(sd + sam[tl] * 384 + og);
                    v10 += f0.x; v11 += f0.y;
                }
                if (t < T_ - 1) {
                    float2 f2 = *(const float2*)(sd + sam[tl + 2] * 384 + 256 + og);
                    v10 += f2.x; v11 += f2.y;
                }
            }
        }
        float* yp = &y[((size_t)b * COUT + og) * T_ + tt];
        yp[0] = v00; yp[8] = v10; yp[T_] = v01; yp[T_ + 8] = v11;

        float s0 = v00 + v10, q0 = fmaf(v00, v00, v10 * v10);
        float s1 = v01 + v11, q1 = fmaf(v01, v01, v11 * v11);
        s0 += __shfl_xor_sync(~0u, s0, 4);  q0 += __shfl_xor_sync(~0u, q0, 4);
        s0 += __shfl_xor_sync(~0u, s0, 8);  q0 += __shfl_xor_sync(~0u, q0, 8);
        s0 += __shfl_xor_sync(~0u, s0, 16); q0 += __shfl_xor_sync(~0u, q0, 16);
        s1 += __shfl_xor_sync(~0u, s1, 4);  q1 += __shfl_xor_sync(~0u, q1, 4);
        s1 += __shfl_xor_sync(~0u, s1, 8);  q1 += __shfl_xor_sync(~0u, q1, 8);
        s1 += __shfl_xor_sync(~0u, s1, 16); q1 += __shfl_xor_sync(~0u, q1, 16);
        if ((lid >> 2) == 0) {
            atomicAdd(&osum[og], s0);     atomicAdd(&osq[og], q0);
            atomicAdd(&osum[og + 1], s1); atomicAdd(&osq[og + 1], q1);
        }
    }
}

// ------------------------- GN finalize -------------------------------------
template <int S>
__global__ void __launch_bounds__(256) k_gnfin() {
    constexpr int COUT = (S == 1) ? C1 : (S == 2) ? C2 : C3;
    constexpr int CPG = COUT / 32;
    const int i = blockIdx.x * 256 + threadIdx.x;
    if (i >= NB * 32) return;
    const int b = i / 32, g = i % 32;
    const float* os = d_osum + (S - 1) * NB * 128 + b * COUT + g * CPG;
    const float* oq = d_osq  + (S - 1) * NB * 128 + b * COUT + g * CPG;
    float s = 0.f, q = 0.f;
#pragma unroll
    for (int j = 0; j < CPG; j++) { s += os[j]; q += oq[j]; }
    const float N = (float)(CPG * T_);
    const float m = s / N;
    d_meanA[(S - 1) * NB * 32 + i] = m;
    d_rstdA[(S - 1) * NB * 32 + i] = rsqrtf(q / N - m * m + 1e-5f);
}

// ------------------------- conv4 (k=1) + output affine ---------------------
__global__ void __launch_bounds__(256)
k_out(const float* __restrict__ w4, const float* __restrict__ b4,
      const float* __restrict__ s3, const float* __restrict__ bb3,
      const float* __restrict__ omean, const float* __restrict__ ostd,
      float* __restrict__ out) {
    const int b = blockIdx.y;
    const int t = blockIdx.x * 256 + threadIdx.x;
    __shared__ float A[32], Bc[32], W[32];
    if (threadIdx.x < 32) {
        const int c = threadIdx.x;
        const float a = d_rstdA[2 * NB * 32 + b * 32 + c] * s3[c];
        A[c] = a;
        Bc[c] = bb3[c] - d_meanA[2 * NB * 32 + b * 32 + c] * a;
        W[c] = w4[c];
    }
    __syncthreads();
    float acc = b4[0];
#pragma unroll
    for (int c = 0; c < 32; c++) {
        float v = d_y3[(b * 32 + c) * T_ + t];
        v = fmaxf(fmaf(v, A[c], Bc[c]), 0.f);
        acc = fmaf(W[c], v, acc);
    }
    out[(size_t)t * NB + b] = fmaf(acc, ostd[0], omean[0]);
}

// ------------------------- launch ------------------------------------------
constexpr int SROW1 = 96 * 2 + 16, SROW2 = 128 * 2 + 16, SROW3 = 64 * 2 + 16;
constexpr int SM1 = 2 * 66 * SROW1 + 128 * SROW1 + 512;    // ~54.7 KB
constexpr int SM2 = 2 * 66 * SROW2 + 64 * SROW2 + 2048;    // ~55.4 KB
constexpr int SM3 = 2 * 130 * SROW3 + 32 * SROW3 + 1024;   // ~43.1 KB
constexpr int SMSD = (64 * 384 + 80 * 64) * 4;             // ~116 KB

extern "C" void kernel_launch(void* const* d_in, const int* in_sizes, int n_in,
                              void* d_out, int out_size) {
    const float* input      = (const float*)d_in[0];
    const float* g_style    = (const float*)d_in[1];
    const float* char_style = (const float*)d_in[3];
    const float* c1w = (const float*)d_in[4];
    const float* c1b = (const float*)d_in[5];
    const float* g1s = (const float*)d_in[6];
    const float* g1b = (const float*)d_in[7];
    const float* c2w = (const float*)d_in[8];
    const float* c2b = (const float*)d_in[9];
    const float* g2s = (const float*)d_in[10];
    const float* g2b = (const float*)d_in[11];
    const float* c3w = (const float*)d_in[12];
    const float* c3b = (const float*)d_in[13];
    const float* g3s = (const float*)d_in[14];
    const float* g3b = (const float*)d_in[15];
    const float* c4w = (const float*)d_in[16];
    const float* c4b = (const float*)d_in[17];
    const float* om  = (const float*)d_in[18];
    const float* os  = (const float*)d_in[19];
    float* out = (float*)d_out;

    cudaFuncSetAttribute(k_cmma<1>, cudaFuncAttributeMaxDynamicSharedMemorySize, SM1);
    cudaFuncSetAttribute(k_cmma<2>, cudaFuncAttributeMaxDynamicSharedMemorySize, SM2);
    cudaFuncSetAttribute(k_cmma<3>, cudaFuncAttributeMaxDynamicSharedMemorySize, SM3);
    cudaFuncSetAttribute(k_sdot,    cudaFuncAttributeMaxDynamicSharedMemorySize, SMSD);

    k_prep0<<<T_ * NB / 256, 256>>>(input, c1w, c2w, c3w);          // 1
    k_gdot<<<NB, 384>>>(g_style, c1w, c1b);                         // 2
    k_sdot<<<NB, 256, SMSD>>>(char_style, c1w);                     // 3

    k_cmma<1><<<dim3(16, NB), 256, SM1>>>(input, nullptr, nullptr); // 4
    k_gnfin<1><<<(NB * 32 + 255) / 256, 256>>>();

    k_cmma<2><<<dim3(16, NB), 256, SM2>>>(g1s, g1b, c2b);
    k_gnfin<2><<<(NB * 32 + 255) / 256, 256>>>();

    k_cmma<3><<<dim3(8, NB), 256, SM3>>>(g2s, g2b, c3b);
    k_gnfin<3><<<(NB * 32 + 255) / 256, 256>>>();

    k_out<<<dim3(T_ / 256, NB), 256>>>(c4w, c4b, g3s, g3b, om, os, out);
}